// round 9
// baseline (speedup 1.0000x reference)
#include <cuda_runtime.h>
#include <math.h>
#include <stdint.h>

#define G    512
#define NPG  90
#define NTOT (G*NPG)      // 46080
#define FIN  90
#define HC   64
#define KP   70
#define POOLW (KP*HC)     // 4480

// ---------------- scratch (device globals; referenced ONLY in device code) --
__device__ float g_A[G*NPG*NPG];     // RAW edge counts (row = dst), 16.6MB
__device__ float g_PQ[NTOT*128];     // [x@W1l | x@W1r]
__device__ float g_H1[NTOT*HC];      // conv1 output (x_train)
__device__ float g_RW[NTOT*128];     // [relu(h1)@W2l | relu(h1)@W2r]
__device__ float g_pool[G*POOLW];    // sort-pooled features
__device__ int   g_mode;             // 1 = edge data is int64 (odd words zero)

// ---------------- tf32 helpers ----------------------------------------------
__device__ __forceinline__ uint32_t f2tf32(float x) {
    uint32_t r;
    asm("cvt.rna.tf32.f32 %0, %1;" : "=r"(r) : "f"(x));
    return r;
}
__device__ __forceinline__ void split_tf32(float x, uint32_t& hi, uint32_t& lo) {
    hi = f2tf32(x);
    lo = f2tf32(x - __uint_as_float(hi));
}
__device__ __forceinline__ void mma_tf32(float* d, const uint32_t* a,
                                         uint32_t b0, uint32_t b1) {
    asm volatile(
        "mma.sync.aligned.m16n8k8.row.col.f32.tf32.tf32.f32 "
        "{%0,%1,%2,%3},{%4,%5,%6,%7},{%8,%9},{%0,%1,%2,%3};"
        : "+f"(d[0]), "+f"(d[1]), "+f"(d[2]), "+f"(d[3])
        : "r"(a[0]), "r"(a[1]), "r"(a[2]), "r"(a[3]), "r"(b0), "r"(b1));
}

// ---------------- zero adjacency + edge dtype detection ---------------------
__global__ void zeroA_kernel(const int* __restrict__ ei) {
    if (blockIdx.x == 0 && threadIdx.x < 32) {
        int lane = threadIdx.x;
        int nz = 0;
        for (int i = lane; i < 512; i += 32) nz |= ei[2*i + 1];
        unsigned any = __ballot_sync(0xffffffffu, nz != 0);
        if (lane == 0) g_mode = (any == 0);
    }
    int n = G*NPG*NPG/4;
    float4* p = (float4*)g_A;
    float4 z = make_float4(0.f, 0.f, 0.f, 0.f);
    for (int i = blockIdx.x*blockDim.x + threadIdx.x; i < n; i += gridDim.x*blockDim.x)
        p[i] = z;
}

__global__ void edge_kernel(const int* __restrict__ ei, int E) {
    int e = blockIdx.x*blockDim.x + threadIdx.x;
    if (e >= E) return;
    int s, d;
    if (g_mode) { s = ei[2*e]; d = ei[2*(E + e)]; }   // int64 storage
    else        { s = ei[e];   d = ei[E + e];      }  // int32 storage
    if ((unsigned)s >= NTOT || (unsigned)d >= NTOT) return;
    int g  = d / NPG;
    int sl = s - g*NPG;
    int dl = d - g*NPG;
    if ((unsigned)sl >= NPG) return;
    atomicAdd(&g_A[(size_t)(g*NPG + dl)*NPG + sl], 1.0f);
}

// ---------------- node GEMM (3xTF32 mma): X[N,KD] @ [Wl|Wr] -> out[N,128] ----
template<int KD, bool RELU, int INSEL, int OUTSEL>
__global__ __launch_bounds__(256) void gemm_mma(const float* __restrict__ Xext,
                                                const float* __restrict__ Wl,
                                                const float* __restrict__ Wr) {
    constexpr int KP96 = ((KD + 15)/16)*16;
    constexpr int NST  = KP96/16;
    __shared__ float    xs[KP96*68];      // A transposed [k][row(64)+pad]
    __shared__ uint32_t whi[16*128];      // W stage, tf32 hi
    __shared__ uint32_t wlo[16*128];      // W stage, tf32 lo

    const float* X = INSEL ? (const float*)g_H1 : Xext;
    float* out = OUTSEL ? g_RW : g_PQ;
    int t = threadIdx.x;
    int r0blk = blockIdx.x * 64;

    for (int idx = t; idx < 64*KD; idx += 256) {
        int r = idx / KD, k = idx - r*KD;
        float v = X[(size_t)(r0blk + r)*KD + k];
        if (RELU) v = fmaxf(v, 0.f);
        xs[k*68 + r] = v;
    }
    if (KP96 > KD) {
        for (int idx = t; idx < (KP96-KD)*68; idx += 256)
            xs[(KD + idx/68)*68 + (idx - (idx/68)*68)] = 0.f;
    }

    int lane = t & 31, wid = t >> 5;
    int gid = lane >> 2, tig = lane & 3;
    int rbase = (wid >> 1) * 16;
    int cbase = (wid & 1) * 64;

    float acc[8][4];
    #pragma unroll
    for (int i = 0; i < 8; i++)
        #pragma unroll
        for (int j = 0; j < 4; j++) acc[i][j] = 0.f;

    for (int s = 0; s < NST; s++) {
        int kt = s*16;
        __syncthreads();
        for (int idx = t; idx < 16*128; idx += 256) {
            int kk = idx >> 7, c = idx & 127;
            int kg = kt + kk;
            float w = 0.f;
            if (kg < KD) w = (c < 64) ? Wl[kg*64 + c] : Wr[kg*64 + (c - 64)];
            uint32_t h, l; split_tf32(w, h, l);
            whi[idx] = h; wlo[idx] = l;
        }
        __syncthreads();

        #pragma unroll
        for (int kt2 = 0; kt2 < 16; kt2 += 8) {
            int kA = kt + kt2;
            float a0 = xs[(kA + tig)*68     + rbase + gid];
            float a1 = xs[(kA + tig)*68     + rbase + gid + 8];
            float a2 = xs[(kA + tig + 4)*68 + rbase + gid];
            float a3 = xs[(kA + tig + 4)*68 + rbase + gid + 8];
            uint32_t ah[4], al[4];
            split_tf32(a0, ah[0], al[0]);
            split_tf32(a1, ah[1], al[1]);
            split_tf32(a2, ah[2], al[2]);
            split_tf32(a3, ah[3], al[3]);
            #pragma unroll
            for (int nt = 0; nt < 8; nt++) {
                int col = cbase + nt*8 + gid;
                uint32_t b0h = whi[(kt2 + tig)*128 + col];
                uint32_t b1h = whi[(kt2 + tig + 4)*128 + col];
                uint32_t b0l = wlo[(kt2 + tig)*128 + col];
                uint32_t b1l = wlo[(kt2 + tig + 4)*128 + col];
                mma_tf32(acc[nt], ah, b0h, b1h);
                mma_tf32(acc[nt], ah, b0l, b1l);
                mma_tf32(acc[nt], al, b0h, b1h);
            }
        }
    }

    #pragma unroll
    for (int nt = 0; nt < 8; nt++) {
        int col  = cbase + nt*8 + 2*tig;
        size_t r0 = (size_t)(r0blk + rbase + gid);
        *(float2*)&out[r0*128 + col]       = make_float2(acc[nt][0], acc[nt][1]);
        *(float2*)&out[(r0 + 8)*128 + col] = make_float2(acc[nt][2], acc[nt][3]);
    }
}

// ---------------- aggregation via tf32 MMA ----------------------------------
// out[96x64] = A[96x96] @ P[96x64]; A = raw counts (EXACT in tf32, 1 rep),
// P split hi/lo (2 passes). mean = acc*inv[row]; + skip + bias in epilogue.
// CONV==1: from g_PQ -> g_H1 (+extra). CONV==2: from g_RW -> rank+pool fused.
template<int CONV>
__global__ __launch_bounds__(192) void aggr_mma(const float* __restrict__ bias,
                                                float* __restrict__ extra) {
    __shared__ uint32_t Asm[96*33];      // A tf32 [row][k-in-stage(32)+pad]
    __shared__ uint32_t phi[32*68];      // P hi [k][col]
    __shared__ uint32_t plo[32*68];      // P lo [k][col]
    __shared__ float    inv[96];
    __shared__ float    key[NPG];
    __shared__ int      rrank[NPG];

    int g = blockIdx.x;
    int t = threadIdx.x;
    int lane = t & 31, wid = t >> 5;                 // 6 warps
    const float* Pg = (CONV == 1 ? g_PQ : g_RW) + (size_t)g*NPG*128;
    const float* Ag = g_A + (size_t)g*NPG*NPG;

    // per-row count sums -> inverse (6 warps sweep 90 rows, gmem reads cached)
    for (int row = wid; row < NPG; row += 6) {
        float s = 0.f;
        for (int j = lane; j < NPG; j += 32) s += Ag[row*NPG + j];
        #pragma unroll
        for (int o = 16; o; o >>= 1) s += __shfl_xor_sync(0xffffffffu, s, o);
        if (lane == 0) inv[row] = 1.0f / fmaxf(s, 1.0f);
    }

    int gid = lane >> 2, tig = lane & 3;
    int rbase = wid * 16;
    int row0 = rbase + gid, row1 = rbase + gid + 8;

    float acc[8][4];
    #pragma unroll
    for (int i = 0; i < 8; i++)
        #pragma unroll
        for (int j = 0; j < 4; j++) acc[i][j] = 0.f;

    for (int ks = 0; ks < 96; ks += 32) {
        __syncthreads();
        // stage A rows x 32 k (zero-pad row/k >= 90)
        for (int idx = t; idx < 96*32; idx += 192) {
            int row = idx >> 5, kk = idx & 31;
            int k = ks + kk;
            float v = (row < NPG && k < NPG) ? Ag[row*NPG + k] : 0.f;
            Asm[row*33 + kk] = f2tf32(v);            // counts: exact
        }
        // stage P hi/lo (zero-pad j >= 90)
        for (int idx = t; idx < 32*64; idx += 192) {
            int kk = idx >> 6, c = idx & 63;
            int j = ks + kk;
            float v = (j < NPG) ? Pg[j*128 + c] : 0.f;
            uint32_t h, l; split_tf32(v, h, l);
            phi[kk*68 + c] = h; plo[kk*68 + c] = l;
        }
        __syncthreads();

        #pragma unroll
        for (int k8 = 0; k8 < 32; k8 += 8) {
            uint32_t a[4];
            a[0] = Asm[row0*33 + k8 + tig];
            a[1] = Asm[row1*33 + k8 + tig];
            a[2] = Asm[row0*33 + k8 + tig + 4];
            a[3] = Asm[row1*33 + k8 + tig + 4];
            #pragma unroll
            for (int nt = 0; nt < 8; nt++) {
                int col = nt*8 + gid;
                uint32_t bh0 = phi[(k8 + tig)*68 + col];
                uint32_t bh1 = phi[(k8 + tig + 4)*68 + col];
                uint32_t bl0 = plo[(k8 + tig)*68 + col];
                uint32_t bl1 = plo[(k8 + tig + 4)*68 + col];
                mma_tf32(acc[nt], a, bh0, bh1);      // A * P_hi
                mma_tf32(acc[nt], a, bl0, bl1);      // A * P_lo
            }
        }
    }

    // epilogue: v = acc*inv + skip + bias
    float i0 = (row0 < NPG) ? inv[row0] : 0.f;
    float i1 = (row1 < NPG) ? inv[row1] : 0.f;
    #pragma unroll
    for (int nt = 0; nt < 8; nt++) {
        int c0 = nt*8 + 2*tig;
        float bc0 = __ldg(&bias[c0]), bc1 = __ldg(&bias[c0 + 1]);
        if (row0 < NPG) {
            acc[nt][0] = acc[nt][0]*i0 + Pg[row0*128 + 64 + c0]     + bc0;
            acc[nt][1] = acc[nt][1]*i0 + Pg[row0*128 + 64 + c0 + 1] + bc1;
        }
        if (row1 < NPG) {
            acc[nt][2] = acc[nt][2]*i1 + Pg[row1*128 + 64 + c0]     + bc0;
            acc[nt][3] = acc[nt][3]*i1 + Pg[row1*128 + 64 + c0 + 1] + bc1;
        }
    }

    if (CONV == 1) {
        #pragma unroll
        for (int nt = 0; nt < 8; nt++) {
            int c0 = nt*8 + 2*tig;
            if (row0 < NPG) {
                size_t o0 = (size_t)(g*NPG + row0)*HC + c0;
                *(float2*)&g_H1[o0] = make_float2(acc[nt][0], acc[nt][1]);
                if (extra) *(float2*)&extra[o0] = make_float2(acc[nt][0], acc[nt][1]);
            }
            if (row1 < NPG) {
                size_t o1 = (size_t)(g*NPG + row1)*HC + c0;
                *(float2*)&g_H1[o1] = make_float2(acc[nt][2], acc[nt][3]);
                if (extra) *(float2*)&extra[o1] = make_float2(acc[nt][2], acc[nt][3]);
            }
        }
    } else {
        // sort key = channel 63 -> nt=7, tig=3 holds cols 62,63
        if (tig == 3) {
            if (row0 < NPG) key[row0] = acc[7][1];
            if (row1 < NPG) key[row1] = acc[7][3];
        }
        __syncthreads();
        if (t < NPG) {
            float v = key[t];
            int rank = 0;
            for (int j = 0; j < NPG; j++) {
                float u = key[j];
                rank += (u > v) || (u == v && j < t);
            }
            rrank[t] = rank;
        }
        __syncthreads();
        int rk0 = (row0 < NPG) ? rrank[row0] : KP;
        int rk1 = (row1 < NPG) ? rrank[row1] : KP;
        #pragma unroll
        for (int nt = 0; nt < 8; nt++) {
            int c0 = nt*8 + 2*tig;
            if (rk0 < KP)
                *(float2*)&g_pool[(size_t)g*POOLW + rk0*HC + c0] =
                    make_float2(acc[nt][0], acc[nt][1]);
            if (rk1 < KP)
                *(float2*)&g_pool[(size_t)g*POOLW + rk1*HC + c0] =
                    make_float2(acc[nt][2], acc[nt][3]);
        }
    }
}

// ---------------- final: pool @ Wl1 + bl1, @ Wl2 + bl2, sigmoid -------------
__global__ __launch_bounds__(256) void final_kernel(const float* __restrict__ Wl1,
                                                    const float* __restrict__ bl1,
                                                    const float* __restrict__ Wl2,
                                                    const float* __restrict__ bl2,
                                                    float* __restrict__ outG) {
    __shared__ float ws[64*64];
    __shared__ float ps[8*64];
    __shared__ float pbuf[8*64];
    int t = threadIdx.x;
    int g0 = blockIdx.x * 8;
    int c = t & 63, gi = t >> 6;
    float acc0 = 0.f, acc1 = 0.f;

    for (int chunk = 0; chunk < POOLW/64; chunk++) {
        int m0 = chunk*64;
        __syncthreads();
        for (int idx = t; idx < 64*64; idx += 256)
            ws[idx] = Wl1[(size_t)(m0 + (idx >> 6))*64 + (idx & 63)];
        for (int idx = t; idx < 8*64; idx += 256) {
            int gg = idx >> 6, mm = idx & 63;
            ps[idx] = g_pool[(size_t)(g0 + gg)*POOLW + m0 + mm];
        }
        __syncthreads();
        #pragma unroll
        for (int kk = 0; kk < 64; kk++) {
            float w = ws[kk*64 + c];
            acc0 += ps[gi*64 + kk] * w;
            acc1 += ps[(gi+4)*64 + kk] * w;
        }
    }
    __syncthreads();
    pbuf[gi*64 + c]     = acc0 + bl1[c];
    pbuf[(gi+4)*64 + c] = acc1 + bl1[c];
    __syncthreads();
    int w = t >> 5, lane = t & 31;
    float v = pbuf[w*64 + lane]*Wl2[lane] + pbuf[w*64 + lane + 32]*Wl2[lane + 32];
    #pragma unroll
    for (int o = 16; o; o >>= 1) v += __shfl_xor_sync(0xffffffffu, v, o);
    if (lane == 0) outG[g0 + w] = 1.f / (1.f + expf(-(v + bl2[0])));
}

// ---------------------------------------------------------------------------
extern "C" void kernel_launch(void* const* d_in, const int* in_sizes, int n_in,
                              void* d_out, int out_size) {
    const float *x = 0, *W1l = 0, *W1r = 0, *W2l = 0, *W2r = 0;
    const float *Wl1 = 0, *bl2 = 0;
    const int   *ei = 0;
    int i5760 = 0, i4096 = 0;
    int idx64[8]; int n64 = 0;

    for (int i = 0; i < n_in; i++) {
        int sz = in_sizes[i];
        const float* p = (const float*)d_in[i];
        switch (sz) {
            case 4147200: x   = p; break;                       // [46080,90]
            case 1843200: ei  = (const int*)d_in[i]; break;     // [2,921600]
            case  286720: Wl1 = p; break;                       // [4480,64]
            case    5760: if (i5760++ == 0) W1l = p; else W1r = p; break;
            case    4096: if (i4096++ == 0) W2l = p; else W2r = p; break;
            case      64: if (n64 < 8) idx64[n64++] = i; break; // b1,b2,bl1,Wl2
            case       1: bl2 = p; break;
            default: break;                                     // batch unused
        }
    }
    const float *b1, *b2, *bl1, *Wl2;
    if (n_in > 0 && in_sizes[0] == 5760) {          // alphabetical (W* first)
        Wl2 = (const float*)d_in[idx64[0]];
        b1  = (const float*)d_in[idx64[1]];
        b2  = (const float*)d_in[idx64[2]];
        bl1 = (const float*)d_in[idx64[3]];
    } else {                                        // dict / signature order
        b1  = (const float*)d_in[idx64[0]];
        b2  = (const float*)d_in[idx64[1]];
        bl1 = (const float*)d_in[idx64[2]];
        Wl2 = (const float*)d_in[idx64[3]];
    }

    float* outG = (float*)d_out;
    float* xtp  = (out_size >= G + NTOT*HC) ? (float*)d_out + G : (float*)0;
    int E = 1843200 / 2;

    // (1) zero adjacency + detect edge dtype
    zeroA_kernel<<<2048, 512>>>(ei);
    // (2) edge counts
    edge_kernel<<<(E + 255)/256, 256>>>(ei, E);
    // (3) conv1 projections (3xTF32 tensor cores)
    gemm_mma<90, false, 0, 0><<<NTOT/64, 256>>>(x, W1l, W1r);
    // (4) conv1 aggregation via MMA  [<- ncu capture slot]
    aggr_mma<1><<<G, 192>>>(b1, xtp);
    // (5) conv2 projections (relu on load)
    gemm_mma<64, true, 1, 1><<<NTOT/64, 256>>>((const float*)0, W2l, W2r);
    // (6) conv2 aggregation + sort-pool fused (MMA)
    aggr_mma<2><<<G, 192>>>(b2, (float*)0);
    // (7) MLP head
    final_kernel<<<G/8, 256>>>(Wl1, bl1, Wl2, bl2, outG);
}

// round 11
// speedup vs baseline: 1.1729x; 1.1729x over previous
#include <cuda_runtime.h>
#include <math.h>
#include <stdint.h>

#define G    512
#define NPG  90
#define NTOT (G*NPG)      // 46080
#define FIN  90
#define HC   64
#define KP   70
#define POOLW (KP*HC)     // 4480

// ---------------- scratch (device globals; referenced ONLY in device code) --
__device__ float g_A[G*NPG*NPG];     // RAW edge counts (row = dst), 16.6MB
__device__ float g_PQ[NTOT*128];     // [x@W1l | x@W1r]
__device__ float g_H1[NTOT*HC];      // conv1 output (x_train)
__device__ float g_RW[NTOT*128];     // [relu(h1)@W2l | relu(h1)@W2r]
__device__ float g_pool[G*POOLW];    // sort-pooled features
__device__ int   g_mode;             // 1 = edge data is int64 (odd words zero)

// ---------------- tf32 helpers ----------------------------------------------
__device__ __forceinline__ uint32_t f2tf32(float x) {
    uint32_t r;
    asm("cvt.rna.tf32.f32 %0, %1;" : "=r"(r) : "f"(x));
    return r;
}
__device__ __forceinline__ void split_tf32(float x, uint32_t& hi, uint32_t& lo) {
    hi = f2tf32(x);
    lo = f2tf32(x - __uint_as_float(hi));
}
__device__ __forceinline__ void mma_tf32(float* d, const uint32_t* a,
                                         uint32_t b0, uint32_t b1) {
    asm volatile(
        "mma.sync.aligned.m16n8k8.row.col.f32.tf32.tf32.f32 "
        "{%0,%1,%2,%3},{%4,%5,%6,%7},{%8,%9},{%0,%1,%2,%3};"
        : "+f"(d[0]), "+f"(d[1]), "+f"(d[2]), "+f"(d[3])
        : "r"(a[0]), "r"(a[1]), "r"(a[2]), "r"(a[3]), "r"(b0), "r"(b1));
}

// ---------------- zero adjacency + edge dtype detection ---------------------
__global__ void zeroA_kernel(const int* __restrict__ ei) {
    if (blockIdx.x == 0 && threadIdx.x < 32) {
        int lane = threadIdx.x;
        int nz = 0;
        for (int i = lane; i < 512; i += 32) nz |= ei[2*i + 1];
        unsigned any = __ballot_sync(0xffffffffu, nz != 0);
        if (lane == 0) g_mode = (any == 0);
    }
    int n = G*NPG*NPG/4;
    float4* p = (float4*)g_A;
    float4 z = make_float4(0.f, 0.f, 0.f, 0.f);
    for (int i = blockIdx.x*blockDim.x + threadIdx.x; i < n; i += gridDim.x*blockDim.x)
        p[i] = z;
}

__global__ void edge_kernel(const int* __restrict__ ei, int E) {
    int e = blockIdx.x*blockDim.x + threadIdx.x;
    if (e >= E) return;
    int s, d;
    if (g_mode) { s = ei[2*e]; d = ei[2*(E + e)]; }   // int64 storage
    else        { s = ei[e];   d = ei[E + e];      }  // int32 storage
    if ((unsigned)s >= NTOT || (unsigned)d >= NTOT) return;
    int g  = d / NPG;
    int sl = s - g*NPG;
    int dl = d - g*NPG;
    if ((unsigned)sl >= NPG) return;
    atomicAdd(&g_A[(size_t)(g*NPG + dl)*NPG + sl], 1.0f);
}

// ---------------- node GEMM (3xTF32 mma): X[N,KD] @ [Wl|Wr] -> out[N,128] ----
// 32-k W stages (pitch 132: conflict-free B reads), 64 rows/block, 8 warps.
template<int KD, bool RELU, int INSEL, int OUTSEL>
__global__ __launch_bounds__(256) void gemm_mma(const float* __restrict__ Xext,
                                                const float* __restrict__ Wl,
                                                const float* __restrict__ Wr) {
    constexpr int KP96 = ((KD + 31)/32)*32;   // 96 (KD=90) or 64 (KD=64)
    constexpr int NST  = KP96/32;
    __shared__ float    xs[KP96*68];          // A transposed [k][row(64)+pad]
    __shared__ uint32_t whi[32*132];          // W stage hi (pitch 132)
    __shared__ uint32_t wlo[32*132];          // W stage lo

    const float* X = INSEL ? (const float*)g_H1 : Xext;
    float* out = OUTSEL ? g_RW : g_PQ;
    int t = threadIdx.x;
    int r0blk = blockIdx.x * 64;

    for (int idx = t; idx < 64*KD; idx += 256) {
        int r = idx / KD, k = idx - r*KD;
        float v = X[(size_t)(r0blk + r)*KD + k];
        if (RELU) v = fmaxf(v, 0.f);
        xs[k*68 + r] = v;
    }
    if (KP96 > KD) {
        for (int idx = t; idx < (KP96-KD)*68; idx += 256)
            xs[(KD + idx/68)*68 + (idx - (idx/68)*68)] = 0.f;
    }

    int lane = t & 31, wid = t >> 5;
    int gid = lane >> 2, tig = lane & 3;
    int rbase = (wid >> 1) * 16;
    int cbase = (wid & 1) * 64;

    float acc[8][4];
    #pragma unroll
    for (int i = 0; i < 8; i++)
        #pragma unroll
        for (int j = 0; j < 4; j++) acc[i][j] = 0.f;

    for (int s = 0; s < NST; s++) {
        int kt = s*32;
        __syncthreads();   // protects prev-stage whi/wlo; 1st iter covers xs
        for (int idx = t; idx < 32*128; idx += 256) {
            int kk = idx >> 7, c = idx & 127;
            int kg = kt + kk;
            float w = 0.f;
            if (kg < KD) w = (c < 64) ? Wl[kg*64 + c] : Wr[kg*64 + (c - 64)];
            uint32_t h, l; split_tf32(w, h, l);
            whi[kk*132 + c] = h; wlo[kk*132 + c] = l;
        }
        __syncthreads();

        #pragma unroll
        for (int kt2 = 0; kt2 < 32; kt2 += 8) {
            int kA = kt + kt2;
            float a0 = xs[(kA + tig)*68     + rbase + gid];
            float a1 = xs[(kA + tig)*68     + rbase + gid + 8];
            float a2 = xs[(kA + tig + 4)*68 + rbase + gid];
            float a3 = xs[(kA + tig + 4)*68 + rbase + gid + 8];
            uint32_t ah[4], al[4];
            split_tf32(a0, ah[0], al[0]);
            split_tf32(a1, ah[1], al[1]);
            split_tf32(a2, ah[2], al[2]);
            split_tf32(a3, ah[3], al[3]);
            #pragma unroll
            for (int nt = 0; nt < 8; nt++) {
                int col = cbase + nt*8 + gid;
                uint32_t b0h = whi[(kt2 + tig)*132 + col];
                uint32_t b1h = whi[(kt2 + tig + 4)*132 + col];
                uint32_t b0l = wlo[(kt2 + tig)*132 + col];
                uint32_t b1l = wlo[(kt2 + tig + 4)*132 + col];
                mma_tf32(acc[nt], ah, b0h, b1h);
                mma_tf32(acc[nt], ah, b0l, b1l);
                mma_tf32(acc[nt], al, b0h, b1h);
            }
        }
    }

    #pragma unroll
    for (int nt = 0; nt < 8; nt++) {
        int col  = cbase + nt*8 + 2*tig;
        size_t r0 = (size_t)(r0blk + rbase + gid);
        *(float2*)&out[r0*128 + col]       = make_float2(acc[nt][0], acc[nt][1]);
        *(float2*)&out[(r0 + 8)*128 + col] = make_float2(acc[nt][2], acc[nt][3]);
    }
}

// ---------------- aggregation via tf32 MMA, full upfront staging -------------
// 12 warps: warps 0-5 cols 0-31, warps 6-11 cols 32-63; rows (w%6)*16..+16.
// A counts exact in tf32 (1 rep), P split hi/lo (2 passes). One load phase.
// CONV==1: g_PQ -> g_H1 (+extra). CONV==2: g_RW -> rank+pool fused.
template<int CONV>
__global__ __launch_bounds__(384) void aggr_mma(const float* __restrict__ bias,
                                                float* __restrict__ extra) {
    __shared__ uint32_t Asm[96*100];     // A tf32, pitch 100 (conflict-free)
    __shared__ uint32_t phi[96*68];      // P hi, pitch 68 (conflict-free)
    __shared__ uint32_t plo[96*68];      // P lo
    __shared__ float    inv[96];
    __shared__ float    key[NPG];
    __shared__ int      rrank[NPG];

    int g = blockIdx.x;
    int t = threadIdx.x;
    int lane = t & 31, w = t >> 5;                   // 12 warps
    const float* Pg = (CONV == 1 ? g_PQ : g_RW) + (size_t)g*NPG*128;
    const float* Ag = g_A + (size_t)g*NPG*NPG;

    // ---- stage A: warp w -> rows w*8 .. w*8+7 (full K) ----
    #pragma unroll
    for (int i = 0; i < 8; i++) {
        int r = w*8 + i;
        #pragma unroll
        for (int kk = 0; kk < 3; kk++) {
            int k = lane + kk*32;
            float v = 0.f;
            if (r < NPG && k < NPG) v = Ag[r*NPG + k];
            if (k < 96) Asm[r*100 + k] = f2tf32(v);
        }
    }
    // ---- stage P: warp w -> k-rows w*8 .. w*8+7, cols lane, lane+32 ----
    #pragma unroll
    for (int i = 0; i < 8; i++) {
        int k = w*8 + i;
        #pragma unroll
        for (int cc = 0; cc < 2; cc++) {
            int c = lane + cc*32;
            float v = (k < NPG) ? Pg[k*128 + c] : 0.f;
            uint32_t h, l; split_tf32(v, h, l);
            phi[k*68 + c] = h; plo[k*68 + c] = l;
        }
    }
    __syncthreads();

    // ---- row sums from smem (no extra gmem pass) ----
    #pragma unroll
    for (int i = 0; i < 8; i++) {
        int r = w*8 + i;
        float s = 0.f;
        #pragma unroll
        for (int kk = 0; kk < 3; kk++) {
            int k = lane + kk*32;
            if (k < NPG) s += __uint_as_float(Asm[r*100 + k]);
        }
        #pragma unroll
        for (int o = 16; o; o >>= 1) s += __shfl_xor_sync(0xffffffffu, s, o);
        if (lane == 0) inv[r] = 1.0f / fmaxf(s, 1.0f);
    }
    __syncthreads();

    // ---- MMA: warp = 16 rows x 32 cols ----
    int gid = lane >> 2, tig = lane & 3;
    int wm = (w >= 6) ? (w - 6) : w;
    int colbase = (w >= 6) ? 32 : 0;
    int row0 = wm*16 + gid, row1 = row0 + 8;

    float acc[4][4];
    #pragma unroll
    for (int i = 0; i < 4; i++)
        #pragma unroll
        for (int j = 0; j < 4; j++) acc[i][j] = 0.f;

    #pragma unroll
    for (int k8 = 0; k8 < 96; k8 += 8) {
        uint32_t a[4];
        a[0] = Asm[row0*100 + k8 + tig];
        a[1] = Asm[row1*100 + k8 + tig];
        a[2] = Asm[row0*100 + k8 + tig + 4];
        a[3] = Asm[row1*100 + k8 + tig + 4];
        #pragma unroll
        for (int nt = 0; nt < 4; nt++) {
            int col = colbase + nt*8 + gid;
            uint32_t bh0 = phi[(k8 + tig)*68 + col];
            uint32_t bh1 = phi[(k8 + tig + 4)*68 + col];
            uint32_t bl0 = plo[(k8 + tig)*68 + col];
            uint32_t bl1 = plo[(k8 + tig + 4)*68 + col];
            mma_tf32(acc[nt], a, bh0, bh1);
            mma_tf32(acc[nt], a, bl0, bl1);
        }
    }

    // ---- epilogue: v = acc*inv + skip + bias ----
    float i0 = (row0 < NPG) ? inv[row0] : 0.f;
    float i1 = (row1 < NPG) ? inv[row1] : 0.f;
    #pragma unroll
    for (int nt = 0; nt < 4; nt++) {
        int c0 = colbase + nt*8 + 2*tig;
        float bc0 = __ldg(&bias[c0]), bc1 = __ldg(&bias[c0 + 1]);
        if (row0 < NPG) {
            acc[nt][0] = acc[nt][0]*i0 + Pg[row0*128 + 64 + c0]     + bc0;
            acc[nt][1] = acc[nt][1]*i0 + Pg[row0*128 + 64 + c0 + 1] + bc1;
        }
        if (row1 < NPG) {
            acc[nt][2] = acc[nt][2]*i1 + Pg[row1*128 + 64 + c0]     + bc0;
            acc[nt][3] = acc[nt][3]*i1 + Pg[row1*128 + 64 + c0 + 1] + bc1;
        }
    }

    if (CONV == 1) {
        #pragma unroll
        for (int nt = 0; nt < 4; nt++) {
            int c0 = colbase + nt*8 + 2*tig;
            if (row0 < NPG) {
                size_t o0 = (size_t)(g*NPG + row0)*HC + c0;
                *(float2*)&g_H1[o0] = make_float2(acc[nt][0], acc[nt][1]);
                if (extra) *(float2*)&extra[o0] = make_float2(acc[nt][0], acc[nt][1]);
            }
            if (row1 < NPG) {
                size_t o1 = (size_t)(g*NPG + row1)*HC + c0;
                *(float2*)&g_H1[o1] = make_float2(acc[nt][2], acc[nt][3]);
                if (extra) *(float2*)&extra[o1] = make_float2(acc[nt][2], acc[nt][3]);
            }
        }
    } else {
        // key = channel 63: warps 6-11, nt=3, tig=3 hold cols 62,63
        if (w >= 6 && tig == 3) {
            if (row0 < NPG) key[row0] = acc[3][1];
            if (row1 < NPG) key[row1] = acc[3][3];
        }
        __syncthreads();
        if (t < NPG) {
            float v = key[t];
            int rank = 0;
            for (int j = 0; j < NPG; j++) {
                float u = key[j];
                rank += (u > v) || (u == v && j < t);
            }
            rrank[t] = rank;
        }
        __syncthreads();
        int rk0 = (row0 < NPG) ? rrank[row0] : KP;
        int rk1 = (row1 < NPG) ? rrank[row1] : KP;
        #pragma unroll
        for (int nt = 0; nt < 4; nt++) {
            int c0 = colbase + nt*8 + 2*tig;
            if (rk0 < KP)
                *(float2*)&g_pool[(size_t)g*POOLW + rk0*HC + c0] =
                    make_float2(acc[nt][0], acc[nt][1]);
            if (rk1 < KP)
                *(float2*)&g_pool[(size_t)g*POOLW + rk1*HC + c0] =
                    make_float2(acc[nt][2], acc[nt][3]);
        }
    }
}

// ---------------- final: pool @ Wl1 + bl1, @ Wl2 + bl2, sigmoid -------------
__global__ __launch_bounds__(256) void final_kernel(const float* __restrict__ Wl1,
                                                    const float* __restrict__ bl1,
                                                    const float* __restrict__ Wl2,
                                                    const float* __restrict__ bl2,
                                                    float* __restrict__ outG) {
    __shared__ float ws[64*64];
    __shared__ float ps[8*64];
    __shared__ float pbuf[8*64];
    int t = threadIdx.x;
    int g0 = blockIdx.x * 8;
    int c = t & 63, gi = t >> 6;
    float acc0 = 0.f, acc1 = 0.f;

    for (int chunk = 0; chunk < POOLW/64; chunk++) {
        int m0 = chunk*64;
        __syncthreads();
        for (int idx = t; idx < 64*64; idx += 256)
            ws[idx] = Wl1[(size_t)(m0 + (idx >> 6))*64 + (idx & 63)];
        for (int idx = t; idx < 8*64; idx += 256) {
            int gg = idx >> 6, mm = idx & 63;
            ps[idx] = g_pool[(size_t)(g0 + gg)*POOLW + m0 + mm];
        }
        __syncthreads();
        #pragma unroll
        for (int kk = 0; kk < 64; kk++) {
            float w = ws[kk*64 + c];
            acc0 += ps[gi*64 + kk] * w;
            acc1 += ps[(gi+4)*64 + kk] * w;
        }
    }
    __syncthreads();
    pbuf[gi*64 + c]     = acc0 + bl1[c];
    pbuf[(gi+4)*64 + c] = acc1 + bl1[c];
    __syncthreads();
    int w = t >> 5, lane = t & 31;
    float v = pbuf[w*64 + lane]*Wl2[lane] + pbuf[w*64 + lane + 32]*Wl2[lane + 32];
    #pragma unroll
    for (int o = 16; o; o >>= 1) v += __shfl_xor_sync(0xffffffffu, v, o);
    if (lane == 0) outG[g0 + w] = 1.f / (1.f + expf(-(v + bl2[0])));
}

// ---------------------------------------------------------------------------
extern "C" void kernel_launch(void* const* d_in, const int* in_sizes, int n_in,
                              void* d_out, int out_size) {
    const float *x = 0, *W1l = 0, *W1r = 0, *W2l = 0, *W2r = 0;
    const float *Wl1 = 0, *bl2 = 0;
    const int   *ei = 0;
    int i5760 = 0, i4096 = 0;
    int idx64[8]; int n64 = 0;

    for (int i = 0; i < n_in; i++) {
        int sz = in_sizes[i];
        const float* p = (const float*)d_in[i];
        switch (sz) {
            case 4147200: x   = p; break;                       // [46080,90]
            case 1843200: ei  = (const int*)d_in[i]; break;     // [2,921600]
            case  286720: Wl1 = p; break;                       // [4480,64]
            case    5760: if (i5760++ == 0) W1l = p; else W1r = p; break;
            case    4096: if (i4096++ == 0) W2l = p; else W2r = p; break;
            case      64: if (n64 < 8) idx64[n64++] = i; break; // b1,b2,bl1,Wl2
            case       1: bl2 = p; break;
            default: break;                                     // batch unused
        }
    }
    const float *b1, *b2, *bl1, *Wl2;
    if (n_in > 0 && in_sizes[0] == 5760) {          // alphabetical (W* first)
        Wl2 = (const float*)d_in[idx64[0]];
        b1  = (const float*)d_in[idx64[1]];
        b2  = (const float*)d_in[idx64[2]];
        bl1 = (const float*)d_in[idx64[3]];
    } else {                                        // dict / signature order
        b1  = (const float*)d_in[idx64[0]];
        b2  = (const float*)d_in[idx64[1]];
        bl1 = (const float*)d_in[idx64[2]];
        Wl2 = (const float*)d_in[idx64[3]];
    }

    float* outG = (float*)d_out;
    float* xtp  = (out_size >= G + NTOT*HC) ? (float*)d_out + G : (float*)0;
    int E = 1843200 / 2;

    // (1) zero adjacency + detect edge dtype
    zeroA_kernel<<<2048, 512>>>(ei);
    // (2) edge counts
    edge_kernel<<<(E + 255)/256, 256>>>(ei, E);
    // (3) conv1 projections (3xTF32 tensor cores)
    gemm_mma<90, false, 0, 0><<<NTOT/64, 256>>>(x, W1l, W1r);
    // (4) conv1 aggregation via MMA, full staging  [<- ncu capture slot]
    aggr_mma<1><<<G, 384>>>(b1, xtp);
    // (5) conv2 projections (relu on load)
    gemm_mma<64, true, 1, 1><<<NTOT/64, 256>>>((const float*)0, W2l, W2r);
    // (6) conv2 aggregation + sort-pool fused (MMA)
    aggr_mma<2><<<G, 384>>>(b2, (float*)0);
    // (7) MLP head
    final_kernel<<<G/8, 256>>>(Wl1, bl1, Wl2, bl2, outG);
}

// round 12
// speedup vs baseline: 1.3700x; 1.1681x over previous
#include <cuda_runtime.h>
#include <math.h>
#include <stdint.h>

#define G    512
#define NPG  90
#define NTOT (G*NPG)      // 46080
#define FIN  90
#define HC   64
#define KP   70
#define POOLW (KP*HC)     // 4480

// ---------------- scratch (device globals; referenced ONLY in device code) --
__device__ float g_A[G*NPG*NPG];     // RAW edge counts (row = dst), 16.6MB
__device__ float g_H1[NTOT*HC];      // conv1 output (x_train)
__device__ float g_pool[G*POOLW];    // sort-pooled features
__device__ int   g_mode;             // 1 = edge data is int64 (odd words zero)

// ---------------- tf32 helpers ----------------------------------------------
__device__ __forceinline__ uint32_t f2tf32(float x) {
    uint32_t r;
    asm("cvt.rna.tf32.f32 %0, %1;" : "=r"(r) : "f"(x));
    return r;
}
__device__ __forceinline__ void split_tf32(float x, uint32_t& hi, uint32_t& lo) {
    hi = f2tf32(x);
    lo = f2tf32(x - __uint_as_float(hi));
}
__device__ __forceinline__ void mma_tf32(float* d, const uint32_t* a,
                                         uint32_t b0, uint32_t b1) {
    asm volatile(
        "mma.sync.aligned.m16n8k8.row.col.f32.tf32.tf32.f32 "
        "{%0,%1,%2,%3},{%4,%5,%6,%7},{%8,%9},{%0,%1,%2,%3};"
        : "+f"(d[0]), "+f"(d[1]), "+f"(d[2]), "+f"(d[3])
        : "r"(a[0]), "r"(a[1]), "r"(a[2]), "r"(a[3]), "r"(b0), "r"(b1));
}

// ---------------- zero adjacency + edge dtype detection ---------------------
__global__ void zeroA_kernel(const int* __restrict__ ei) {
    if (blockIdx.x == 0 && threadIdx.x < 32) {
        int lane = threadIdx.x;
        int nz = 0;
        for (int i = lane; i < 512; i += 32) nz |= ei[2*i + 1];
        unsigned any = __ballot_sync(0xffffffffu, nz != 0);
        if (lane == 0) g_mode = (any == 0);
    }
    int n = G*NPG*NPG/4;
    float4* p = (float4*)g_A;
    float4 z = make_float4(0.f, 0.f, 0.f, 0.f);
    for (int i = blockIdx.x*blockDim.x + threadIdx.x; i < n; i += gridDim.x*blockDim.x)
        p[i] = z;
}

__global__ void edge_kernel(const int* __restrict__ ei, int E) {
    int e = blockIdx.x*blockDim.x + threadIdx.x;
    if (e >= E) return;
    int s, d;
    if (g_mode) { s = ei[2*e]; d = ei[2*(E + e)]; }   // int64 storage
    else        { s = ei[e];   d = ei[E + e];      }  // int32 storage
    if ((unsigned)s >= NTOT || (unsigned)d >= NTOT) return;
    int g  = d / NPG;
    int sl = s - g*NPG;
    int dl = d - g*NPG;
    if ((unsigned)sl >= NPG) return;
    atomicAdd(&g_A[(size_t)(g*NPG + dl)*NPG + sl], 1.0f);
}

// ---------------- fused conv layer: one block per graph ----------------------
// Phase B: P[90x128] = X[90xKD] @ [Wl|Wr]   (3-pass tf32 MMA, W k-staged)
//   -> P cols 0-63 split hi/lo into smem (B operand), cols 64-127 fp32 (skip)
// Phase C: H = rowmean(A @ P[:,0:64]) + P[:,64:128] + bias (2-pass tf32 MMA)
// LAYER==1: X=x (ext), out -> g_H1 (+extra x_train).  LAYER==2: X=relu(g_H1),
// out -> fused rank + sort-pool scatter into g_pool.
// 12 warps: wm=w%6 -> rows wm*16..+16; w<6: cols 0-63, w>=6: cols 64-127 (B),
// phase C: w<6 cols 0-31, w>=6 cols 32-63.
template<int LAYER>
__global__ __launch_bounds__(384) void conv_fused(const float* __restrict__ Xext,
                                                  const float* __restrict__ Wl,
                                                  const float* __restrict__ Wr,
                                                  const float* __restrict__ bias,
                                                  float* __restrict__ extra) {
    constexpr int KD  = (LAYER == 1) ? 90 : 64;
    constexpr int NST = (LAYER == 1) ? 3 : 2;
    __shared__ uint32_t AX[96*100];          // phase B: X fp32 | phase C: A tf32
    __shared__ uint32_t whi[32*136];         // W stage hi (pitch 136: bank-exact)
    __shared__ uint32_t wlo[32*136];
    __shared__ uint32_t phi[96*72];          // P[:,0:64] hi (pitch 72: bank-exact)
    __shared__ uint32_t plo[96*72];
    __shared__ float    skp[96*68];          // P[:,64:128] fp32
    __shared__ float    inv[96];
    __shared__ float    key[96];
    __shared__ int      rrank[96];

    int g = blockIdx.x, t = threadIdx.x;
    int lane = t & 31, w = t >> 5;
    float* Xs = (float*)AX;

    // ---- stage X (zero-fill covers k/row padding) ----
    for (int i = t; i < 96*100; i += 384) Xs[i] = 0.f;
    __syncthreads();
    const float* Xsrc = (LAYER == 1) ? Xext : (const float*)g_H1;
    for (int i = t; i < NPG*KD; i += 384) {
        int r = i / KD, k = i - r*KD;
        float v = Xsrc[(size_t)(g*NPG + r)*KD + k];
        if (LAYER == 2) v = fmaxf(v, 0.f);
        Xs[r*100 + k] = v;
    }

    int gid = lane >> 2, tig = lane & 3;
    int wm  = (w >= 6) ? w - 6 : w;
    int ch  = (w >= 6) ? 1 : 0;
    int row0 = wm*16 + gid, row1 = row0 + 8;
    int cbase = ch*64;

    float acc[8][4];
    #pragma unroll
    for (int i = 0; i < 8; i++)
        #pragma unroll
        for (int j = 0; j < 4; j++) acc[i][j] = 0.f;

    // ---- phase B: projection ----
    for (int s = 0; s < NST; s++) {
        int kt = s*32;
        __syncthreads();                      // Xs ready (s=0) / prev MMA done
        for (int i = t; i < 32*128; i += 384) {
            int kk = i >> 7, c = i & 127;
            int kg = kt + kk;
            float wv = 0.f;
            if (kg < KD) wv = (c < 64) ? Wl[kg*64 + c] : Wr[kg*64 + (c - 64)];
            uint32_t h, l; split_tf32(wv, h, l);
            whi[kk*136 + c] = h; wlo[kk*136 + c] = l;
        }
        __syncthreads();
        #pragma unroll
        for (int kt2 = 0; kt2 < 32; kt2 += 8) {
            int kA = kt + kt2;
            float a0 = Xs[row0*100 + kA + tig];
            float a1 = Xs[row1*100 + kA + tig];
            float a2 = Xs[row0*100 + kA + tig + 4];
            float a3 = Xs[row1*100 + kA + tig + 4];
            uint32_t ah[4], al[4];
            split_tf32(a0, ah[0], al[0]);
            split_tf32(a1, ah[1], al[1]);
            split_tf32(a2, ah[2], al[2]);
            split_tf32(a3, ah[3], al[3]);
            #pragma unroll
            for (int nt = 0; nt < 8; nt++) {
                int col = cbase + nt*8 + gid;
                uint32_t b0h = whi[(kt2 + tig)*136 + col];
                uint32_t b1h = whi[(kt2 + tig + 4)*136 + col];
                uint32_t b0l = wlo[(kt2 + tig)*136 + col];
                uint32_t b1l = wlo[(kt2 + tig + 4)*136 + col];
                mma_tf32(acc[nt], ah, b0h, b1h);
                mma_tf32(acc[nt], ah, b0l, b1l);
                mma_tf32(acc[nt], al, b0h, b1h);
            }
        }
    }

    // ---- projection epilogue: P -> phi/plo (cols<64) or skp (cols>=64) ----
    // rows 90-95 come from zeroed X -> P==0, safe as B-operand padding.
    if (ch == 0) {
        #pragma unroll
        for (int nt = 0; nt < 8; nt++) {
            int c = nt*8 + 2*tig;
            uint32_t h, l;
            split_tf32(acc[nt][0], h, l); phi[row0*72 + c]     = h; plo[row0*72 + c]     = l;
            split_tf32(acc[nt][1], h, l); phi[row0*72 + c + 1] = h; plo[row0*72 + c + 1] = l;
            split_tf32(acc[nt][2], h, l); phi[row1*72 + c]     = h; plo[row1*72 + c]     = l;
            split_tf32(acc[nt][3], h, l); phi[row1*72 + c + 1] = h; plo[row1*72 + c + 1] = l;
        }
    } else {
        #pragma unroll
        for (int nt = 0; nt < 8; nt++) {
            int c = nt*8 + 2*tig;                      // 0..63 local
            *(float2*)&skp[row0*68 + c] = make_float2(acc[nt][0], acc[nt][1]);
            *(float2*)&skp[row1*68 + c] = make_float2(acc[nt][2], acc[nt][3]);
        }
    }
    __syncthreads();                                   // phi/plo/skp ready; Xs free

    // ---- stage A (counts -> tf32, exact), warp w -> rows w*8..w*8+7 ----
    const float* Ag = g_A + (size_t)g*NPG*NPG;
    #pragma unroll
    for (int i2 = 0; i2 < 8; i2++) {
        int r = w*8 + i2;
        #pragma unroll
        for (int kk = 0; kk < 3; kk++) {
            int k = lane + kk*32;
            float v = (r < NPG && k < NPG) ? Ag[r*NPG + k] : 0.f;
            if (k < 96) AX[r*100 + k] = f2tf32(v);
        }
    }
    // row sums (same warp's rows -> no sync needed before)
    #pragma unroll
    for (int i2 = 0; i2 < 8; i2++) {
        int r = w*8 + i2;
        float s = 0.f;
        #pragma unroll
        for (int kk = 0; kk < 3; kk++) {
            int k = lane + kk*32;
            if (k < 96) s += __uint_as_float(AX[r*100 + k]);
        }
        #pragma unroll
        for (int o = 16; o; o >>= 1) s += __shfl_xor_sync(0xffffffffu, s, o);
        if (lane == 0) inv[r] = 1.0f / fmaxf(s, 1.0f);
    }
    __syncthreads();

    // ---- phase C: aggregation MMA (A exact, P hi/lo 2-pass) ----
    int cb2 = ch*32;
    float ac2[4][4];
    #pragma unroll
    for (int i = 0; i < 4; i++)
        #pragma unroll
        for (int j = 0; j < 4; j++) ac2[i][j] = 0.f;

    #pragma unroll
    for (int k8 = 0; k8 < 96; k8 += 8) {
        uint32_t a[4];
        a[0] = AX[row0*100 + k8 + tig];
        a[1] = AX[row1*100 + k8 + tig];
        a[2] = AX[row0*100 + k8 + tig + 4];
        a[3] = AX[row1*100 + k8 + tig + 4];
        #pragma unroll
        for (int nt = 0; nt < 4; nt++) {
            int col = cb2 + nt*8 + gid;
            uint32_t bh0 = phi[(k8 + tig)*72 + col];
            uint32_t bh1 = phi[(k8 + tig + 4)*72 + col];
            uint32_t bl0 = plo[(k8 + tig)*72 + col];
            uint32_t bl1 = plo[(k8 + tig + 4)*72 + col];
            mma_tf32(ac2[nt], a, bh0, bh1);
            mma_tf32(ac2[nt], a, bl0, bl1);
        }
    }

    // ---- epilogue: v = acc*inv + skip + bias ----
    float i0 = (row0 < NPG) ? inv[row0] : 0.f;
    float i1 = (row1 < NPG) ? inv[row1] : 0.f;
    #pragma unroll
    for (int nt = 0; nt < 4; nt++) {
        int c0 = cb2 + nt*8 + 2*tig;
        float bc0 = __ldg(&bias[c0]), bc1 = __ldg(&bias[c0 + 1]);
        ac2[nt][0] = ac2[nt][0]*i0 + skp[row0*68 + c0]     + bc0;
        ac2[nt][1] = ac2[nt][1]*i0 + skp[row0*68 + c0 + 1] + bc1;
        ac2[nt][2] = ac2[nt][2]*i1 + skp[row1*68 + c0]     + bc0;
        ac2[nt][3] = ac2[nt][3]*i1 + skp[row1*68 + c0 + 1] + bc1;
    }

    if (LAYER == 1) {
        #pragma unroll
        for (int nt = 0; nt < 4; nt++) {
            int c0 = cb2 + nt*8 + 2*tig;
            if (row0 < NPG) {
                size_t o0 = (size_t)(g*NPG + row0)*HC + c0;
                *(float2*)&g_H1[o0] = make_float2(ac2[nt][0], ac2[nt][1]);
                if (extra) *(float2*)&extra[o0] = make_float2(ac2[nt][0], ac2[nt][1]);
            }
            if (row1 < NPG) {
                size_t o1 = (size_t)(g*NPG + row1)*HC + c0;
                *(float2*)&g_H1[o1] = make_float2(ac2[nt][2], ac2[nt][3]);
                if (extra) *(float2*)&extra[o1] = make_float2(ac2[nt][2], ac2[nt][3]);
            }
        }
    } else {
        // key = channel 63: ch==1, nt=3, tig=3 -> cols 62,63
        if (ch == 1 && tig == 3) {
            if (row0 < NPG) key[row0] = ac2[3][1];
            if (row1 < NPG) key[row1] = ac2[3][3];
        }
        __syncthreads();
        if (t < NPG) {
            float v = key[t];
            int rank = 0;
            for (int j = 0; j < NPG; j++) {
                float u = key[j];
                rank += (u > v) || (u == v && j < t);
            }
            rrank[t] = rank;
        }
        __syncthreads();
        int rk0 = (row0 < NPG) ? rrank[row0] : KP;
        int rk1 = (row1 < NPG) ? rrank[row1] : KP;
        #pragma unroll
        for (int nt = 0; nt < 4; nt++) {
            int c0 = cb2 + nt*8 + 2*tig;
            if (rk0 < KP)
                *(float2*)&g_pool[(size_t)g*POOLW + rk0*HC + c0] =
                    make_float2(ac2[nt][0], ac2[nt][1]);
            if (rk1 < KP)
                *(float2*)&g_pool[(size_t)g*POOLW + rk1*HC + c0] =
                    make_float2(ac2[nt][2], ac2[nt][3]);
        }
    }
}

// ---------------- final: pool @ Wl1 + bl1, @ Wl2 + bl2, sigmoid -------------
__global__ __launch_bounds__(256) void final_kernel(const float* __restrict__ Wl1,
                                                    const float* __restrict__ bl1,
                                                    const float* __restrict__ Wl2,
                                                    const float* __restrict__ bl2,
                                                    float* __restrict__ outG) {
    __shared__ float ws[64*64];
    __shared__ float ps[8*64];
    __shared__ float pbuf[8*64];
    int t = threadIdx.x;
    int g0 = blockIdx.x * 8;
    int c = t & 63, gi = t >> 6;
    float acc0 = 0.f, acc1 = 0.f;

    for (int chunk = 0; chunk < POOLW/64; chunk++) {
        int m0 = chunk*64;
        __syncthreads();
        for (int idx = t; idx < 64*64; idx += 256)
            ws[idx] = Wl1[(size_t)(m0 + (idx >> 6))*64 + (idx & 63)];
        for (int idx = t; idx < 8*64; idx += 256) {
            int gg = idx >> 6, mm = idx & 63;
            ps[idx] = g_pool[(size_t)(g0 + gg)*POOLW + m0 + mm];
        }
        __syncthreads();
        #pragma unroll
        for (int kk = 0; kk < 64; kk++) {
            float w = ws[kk*64 + c];
            acc0 += ps[gi*64 + kk] * w;
            acc1 += ps[(gi+4)*64 + kk] * w;
        }
    }
    __syncthreads();
    pbuf[gi*64 + c]     = acc0 + bl1[c];
    pbuf[(gi+4)*64 + c] = acc1 + bl1[c];
    __syncthreads();
    int w = t >> 5, lane = t & 31;
    float v = pbuf[w*64 + lane]*Wl2[lane] + pbuf[w*64 + lane + 32]*Wl2[lane + 32];
    #pragma unroll
    for (int o = 16; o; o >>= 1) v += __shfl_xor_sync(0xffffffffu, v, o);
    if (lane == 0) outG[g0 + w] = 1.f / (1.f + expf(-(v + bl2[0])));
}

// ---------------------------------------------------------------------------
extern "C" void kernel_launch(void* const* d_in, const int* in_sizes, int n_in,
                              void* d_out, int out_size) {
    const float *x = 0, *W1l = 0, *W1r = 0, *W2l = 0, *W2r = 0;
    const float *Wl1 = 0, *bl2 = 0;
    const int   *ei = 0;
    int i5760 = 0, i4096 = 0;
    int idx64[8]; int n64 = 0;

    for (int i = 0; i < n_in; i++) {
        int sz = in_sizes[i];
        const float* p = (const float*)d_in[i];
        switch (sz) {
            case 4147200: x   = p; break;                       // [46080,90]
            case 1843200: ei  = (const int*)d_in[i]; break;     // [2,921600]
            case  286720: Wl1 = p; break;                       // [4480,64]
            case    5760: if (i5760++ == 0) W1l = p; else W1r = p; break;
            case    4096: if (i4096++ == 0) W2l = p; else W2r = p; break;
            case      64: if (n64 < 8) idx64[n64++] = i; break; // b1,b2,bl1,Wl2
            case       1: bl2 = p; break;
            default: break;                                     // batch unused
        }
    }
    const float *b1, *b2, *bl1, *Wl2;
    if (n_in > 0 && in_sizes[0] == 5760) {          // alphabetical (W* first)
        Wl2 = (const float*)d_in[idx64[0]];
        b1  = (const float*)d_in[idx64[1]];
        b2  = (const float*)d_in[idx64[2]];
        bl1 = (const float*)d_in[idx64[3]];
    } else {                                        // dict / signature order
        b1  = (const float*)d_in[idx64[0]];
        b2  = (const float*)d_in[idx64[1]];
        bl1 = (const float*)d_in[idx64[2]];
        Wl2 = (const float*)d_in[idx64[3]];
    }

    float* outG = (float*)d_out;
    float* xtp  = (out_size >= G + NTOT*HC) ? (float*)d_out + G : (float*)0;
    int E = 1843200 / 2;

    // (1) zero adjacency + detect edge dtype
    zeroA_kernel<<<2048, 512>>>(ei);
    // (2) edge counts
    edge_kernel<<<(E + 255)/256, 256>>>(ei, E);
    // (3) conv1 fused: projection + aggregation -> g_H1 (+x_train)
    conv_fused<1><<<G, 384>>>(x, W1l, W1r, b1, xtp);
    // (4) conv2 fused: projection + aggregation + sort-pool -> g_pool
    conv_fused<2><<<G, 384>>>((const float*)0, W2l, W2r, b2, (float*)0);
    // (5) MLP head
    final_kernel<<<G/8, 256>>>(Wl1, bl1, Wl2, bl2, outG);
}

// round 13
// speedup vs baseline: 1.5905x; 1.1609x over previous
#include <cuda_runtime.h>
#include <math.h>
#include <stdint.h>

#define G    512
#define NPG  90
#define NTOT (G*NPG)      // 46080
#define FIN  90
#define HC   64
#define KP   70
#define POOLW (KP*HC)     // 4480

// ---------------- scratch (device globals; referenced ONLY in device code) --
__device__ float g_A[G*NPG*NPG];     // RAW edge counts (row = dst), 16.6MB
__device__ float g_H1[NTOT*HC];      // conv1 output (x_train)
__device__ float g_pool[G*POOLW];    // sort-pooled features
__device__ int   g_mode;             // 1 = edge data is int64 (odd words zero)

// ---------------- tf32 helpers ----------------------------------------------
__device__ __forceinline__ uint32_t f2tf32(float x) {
    uint32_t r;
    asm("cvt.rna.tf32.f32 %0, %1;" : "=r"(r) : "f"(x));
    return r;
}
__device__ __forceinline__ void split_tf32(float x, uint32_t& hi, uint32_t& lo) {
    hi = f2tf32(x);
    lo = f2tf32(x - __uint_as_float(hi));
}
__device__ __forceinline__ void mma_tf32(float* d, const uint32_t* a,
                                         uint32_t b0, uint32_t b1) {
    asm volatile(
        "mma.sync.aligned.m16n8k8.row.col.f32.tf32.tf32.f32 "
        "{%0,%1,%2,%3},{%4,%5,%6,%7},{%8,%9},{%0,%1,%2,%3};"
        : "+f"(d[0]), "+f"(d[1]), "+f"(d[2]), "+f"(d[3])
        : "r"(a[0]), "r"(a[1]), "r"(a[2]), "r"(a[3]), "r"(b0), "r"(b1));
}

// ---------------- zero adjacency + edge dtype detection ---------------------
__global__ void zeroA_kernel(const int* __restrict__ ei) {
    if (blockIdx.x == 0 && threadIdx.x < 32) {
        int lane = threadIdx.x;
        int nz = 0;
        for (int i = lane; i < 512; i += 32) nz |= ei[2*i + 1];
        unsigned any = __ballot_sync(0xffffffffu, nz != 0);
        if (lane == 0) g_mode = (any == 0);
    }
    int n = G*NPG*NPG/4;
    float4* p = (float4*)g_A;
    float4 z = make_float4(0.f, 0.f, 0.f, 0.f);
    for (int i = blockIdx.x*blockDim.x + threadIdx.x; i < n; i += gridDim.x*blockDim.x)
        p[i] = z;
}

__global__ void edge_kernel(const int* __restrict__ ei, int E) {
    int e = blockIdx.x*blockDim.x + threadIdx.x;
    if (e >= E) return;
    int s, d;
    if (g_mode) { s = ei[2*e]; d = ei[2*(E + e)]; }   // int64 storage
    else        { s = ei[e];   d = ei[E + e];      }  // int32 storage
    if ((unsigned)s >= NTOT || (unsigned)d >= NTOT) return;
    int g  = d / NPG;
    int sl = s - g*NPG;
    int dl = d - g*NPG;
    if ((unsigned)sl >= NPG) return;
    atomicAdd(&g_A[(size_t)(g*NPG + dl)*NPG + sl], 1.0f);
}

// ---------------- fused conv layer: one block per graph ----------------------
// Phase B: P[90x128] = X[90xKD] @ [Wl|Wr]   (3-pass tf32 MMA, 16-k W stages)
//   -> P cols 0-63 fp32 to pf (B operand, split on-the-fly), cols 64-127 -> skp
// Phase C: H = rowmean(A @ P[:,0:64]) + skp + bias (2-pass tf32 MMA)
// LAYER==1: X=x (ext), out -> g_H1 (+extra x_train).  LAYER==2: X=relu(g_H1),
// out -> fused rank + sort-pool scatter into g_pool.
// smem ~107KB -> 2 blocks/SM; __launch_bounds__(384,2) caps regs at 85.
template<int LAYER>
__global__ __launch_bounds__(384, 2) void conv_fused(const float* __restrict__ Xext,
                                                     const float* __restrict__ Wl,
                                                     const float* __restrict__ Wr,
                                                     const float* __restrict__ bias,
                                                     float* __restrict__ extra) {
    constexpr int KD  = (LAYER == 1) ? 90 : 64;
    constexpr int NST = (KD + 15)/16;             // 6 or 4 stages of 16 k
    __shared__ uint32_t AX[96*100];          // phase B: X fp32 | phase C: A tf32
    __shared__ uint32_t whi[16*136];         // W stage hi (pitch 136)
    __shared__ uint32_t wlo[16*136];
    __shared__ float    pf [96*68];          // P[:,0:64] fp32 (pitch 68)
    __shared__ float    skp[96*68];          // P[:,64:128] fp32
    __shared__ float    inv[96];
    __shared__ float    key[96];
    __shared__ int      rrank[96];

    int g = blockIdx.x, t = threadIdx.x;
    int lane = t & 31, w = t >> 5;
    float* Xs = (float*)AX;

    // ---- stage X (zero-fill covers k/row padding) ----
    for (int i = t; i < 96*100; i += 384) Xs[i] = 0.f;
    __syncthreads();
    const float* Xsrc = (LAYER == 1) ? Xext : (const float*)g_H1;
    for (int i = t; i < NPG*KD; i += 384) {
        int r = i / KD, k = i - r*KD;
        float v = Xsrc[(size_t)(g*NPG + r)*KD + k];
        if (LAYER == 2) v = fmaxf(v, 0.f);
        Xs[r*100 + k] = v;
    }

    int gid = lane >> 2, tig = lane & 3;
    int wm  = (w >= 6) ? w - 6 : w;
    int ch  = (w >= 6) ? 1 : 0;
    int row0 = wm*16 + gid, row1 = row0 + 8;
    int cbase = ch*64;

    float acc[8][4];
    #pragma unroll
    for (int i = 0; i < 8; i++)
        #pragma unroll
        for (int j = 0; j < 4; j++) acc[i][j] = 0.f;

    // ---- phase B: projection, 16-k W stages ----
    for (int s = 0; s < NST; s++) {
        int kt = s*16;
        __syncthreads();                      // Xs ready (s=0) / prev stage read
        for (int i = t; i < 16*128; i += 384) {
            int kk = i >> 7, c = i & 127;
            int kg = kt + kk;
            float wv = 0.f;
            if (kg < KD) wv = (c < 64) ? Wl[kg*64 + c] : Wr[kg*64 + (c - 64)];
            uint32_t h, l; split_tf32(wv, h, l);
            whi[kk*136 + c] = h; wlo[kk*136 + c] = l;
        }
        __syncthreads();
        #pragma unroll
        for (int kt2 = 0; kt2 < 16; kt2 += 8) {
            int kA = kt + kt2;
            float a0 = Xs[row0*100 + kA + tig];
            float a1 = Xs[row1*100 + kA + tig];
            float a2 = Xs[row0*100 + kA + tig + 4];
            float a3 = Xs[row1*100 + kA + tig + 4];
            uint32_t ah[4], al[4];
            split_tf32(a0, ah[0], al[0]);
            split_tf32(a1, ah[1], al[1]);
            split_tf32(a2, ah[2], al[2]);
            split_tf32(a3, ah[3], al[3]);
            #pragma unroll
            for (int nt = 0; nt < 8; nt++) {
                int col = cbase + nt*8 + gid;
                uint32_t b0h = whi[(kt2 + tig)*136 + col];
                uint32_t b1h = whi[(kt2 + tig + 4)*136 + col];
                uint32_t b0l = wlo[(kt2 + tig)*136 + col];
                uint32_t b1l = wlo[(kt2 + tig + 4)*136 + col];
                mma_tf32(acc[nt], ah, b0h, b1h);
                mma_tf32(acc[nt], ah, b0l, b1l);
                mma_tf32(acc[nt], al, b0h, b1h);
            }
        }
    }

    // ---- projection epilogue: fp32 P -> pf (cols<64) or skp (cols>=64) ----
    // rows 90-95 from zeroed X -> P==0, safe as B-operand padding.
    {
        float* dst = (ch == 0) ? pf : skp;
        #pragma unroll
        for (int nt = 0; nt < 8; nt++) {
            int c = nt*8 + 2*tig;                      // 0..63 local
            *(float2*)&dst[row0*68 + c] = make_float2(acc[nt][0], acc[nt][1]);
            *(float2*)&dst[row1*68 + c] = make_float2(acc[nt][2], acc[nt][3]);
        }
    }
    __syncthreads();                                   // pf/skp ready; Xs free

    // ---- stage A (counts -> tf32, exact), warp w -> rows w*8..w*8+7 ----
    const float* Ag = g_A + (size_t)g*NPG*NPG;
    #pragma unroll
    for (int i2 = 0; i2 < 8; i2++) {
        int r = w*8 + i2;
        #pragma unroll
        for (int kk = 0; kk < 3; kk++) {
            int k = lane + kk*32;
            float v = (r < NPG && k < NPG) ? Ag[r*NPG + k] : 0.f;
            if (k < 96) AX[r*100 + k] = f2tf32(v);
        }
    }
    // row sums (same warp's rows -> no sync needed before)
    #pragma unroll
    for (int i2 = 0; i2 < 8; i2++) {
        int r = w*8 + i2;
        float s = 0.f;
        #pragma unroll
        for (int kk = 0; kk < 3; kk++) {
            int k = lane + kk*32;
            if (k < 96) s += __uint_as_float(AX[r*100 + k]);
        }
        #pragma unroll
        for (int o = 16; o; o >>= 1) s += __shfl_xor_sync(0xffffffffu, s, o);
        if (lane == 0) inv[r] = 1.0f / fmaxf(s, 1.0f);
    }
    __syncthreads();

    // ---- phase C: aggregation MMA (A exact; P split hi/lo on the fly) ----
    int cb2 = ch*32;
    float ac2[4][4];
    #pragma unroll
    for (int i = 0; i < 4; i++)
        #pragma unroll
        for (int j = 0; j < 4; j++) ac2[i][j] = 0.f;

    #pragma unroll
    for (int k8 = 0; k8 < 96; k8 += 8) {
        uint32_t a[4];
        a[0] = AX[row0*100 + k8 + tig];
        a[1] = AX[row1*100 + k8 + tig];
        a[2] = AX[row0*100 + k8 + tig + 4];
        a[3] = AX[row1*100 + k8 + tig + 4];
        #pragma unroll
        for (int nt = 0; nt < 4; nt++) {
            int col = cb2 + nt*8 + gid;
            float b0 = pf[(k8 + tig)*68 + col];
            float b1 = pf[(k8 + tig + 4)*68 + col];
            uint32_t b0h, b0l, b1h, b1l;
            split_tf32(b0, b0h, b0l);
            split_tf32(b1, b1h, b1l);
            mma_tf32(ac2[nt], a, b0h, b1h);
            mma_tf32(ac2[nt], a, b0l, b1l);
        }
    }

    // ---- epilogue: v = acc*inv + skip + bias ----
    float i0 = (row0 < NPG) ? inv[row0] : 0.f;
    float i1 = (row1 < NPG) ? inv[row1] : 0.f;
    #pragma unroll
    for (int nt = 0; nt < 4; nt++) {
        int c0 = cb2 + nt*8 + 2*tig;
        float bc0 = __ldg(&bias[c0]), bc1 = __ldg(&bias[c0 + 1]);
        ac2[nt][0] = ac2[nt][0]*i0 + skp[row0*68 + c0]     + bc0;
        ac2[nt][1] = ac2[nt][1]*i0 + skp[row0*68 + c0 + 1] + bc1;
        ac2[nt][2] = ac2[nt][2]*i1 + skp[row1*68 + c0]     + bc0;
        ac2[nt][3] = ac2[nt][3]*i1 + skp[row1*68 + c0 + 1] + bc1;
    }

    if (LAYER == 1) {
        #pragma unroll
        for (int nt = 0; nt < 4; nt++) {
            int c0 = cb2 + nt*8 + 2*tig;
            if (row0 < NPG) {
                size_t o0 = (size_t)(g*NPG + row0)*HC + c0;
                *(float2*)&g_H1[o0] = make_float2(ac2[nt][0], ac2[nt][1]);
                if (extra) *(float2*)&extra[o0] = make_float2(ac2[nt][0], ac2[nt][1]);
            }
            if (row1 < NPG) {
                size_t o1 = (size_t)(g*NPG + row1)*HC + c0;
                *(float2*)&g_H1[o1] = make_float2(ac2[nt][2], ac2[nt][3]);
                if (extra) *(float2*)&extra[o1] = make_float2(ac2[nt][2], ac2[nt][3]);
            }
        }
    } else {
        // key = channel 63: ch==1, nt=3, tig=3 -> cols 62,63
        if (ch == 1 && tig == 3) {
            if (row0 < NPG) key[row0] = ac2[3][1];
            if (row1 < NPG) key[row1] = ac2[3][3];
        }
        __syncthreads();
        if (t < NPG) {
            float v = key[t];
            int rank = 0;
            for (int j = 0; j < NPG; j++) {
                float u = key[j];
                rank += (u > v) || (u == v && j < t);
            }
            rrank[t] = rank;
        }
        __syncthreads();
        int rk0 = (row0 < NPG) ? rrank[row0] : KP;
        int rk1 = (row1 < NPG) ? rrank[row1] : KP;
        #pragma unroll
        for (int nt = 0; nt < 4; nt++) {
            int c0 = cb2 + nt*8 + 2*tig;
            if (rk0 < KP)
                *(float2*)&g_pool[(size_t)g*POOLW + rk0*HC + c0] =
                    make_float2(ac2[nt][0], ac2[nt][1]);
            if (rk1 < KP)
                *(float2*)&g_pool[(size_t)g*POOLW + rk1*HC + c0] =
                    make_float2(ac2[nt][2], ac2[nt][3]);
        }
    }
}

// ---------------- final: pool @ Wl1 + bl1, @ Wl2 + bl2, sigmoid -------------
__global__ __launch_bounds__(256) void final_kernel(const float* __restrict__ Wl1,
                                                    const float* __restrict__ bl1,
                                                    const float* __restrict__ Wl2,
                                                    const float* __restrict__ bl2,
                                                    float* __restrict__ outG) {
    __shared__ float ws[64*64];
    __shared__ float ps[8*64];
    __shared__ float pbuf[8*64];
    int t = threadIdx.x;
    int g0 = blockIdx.x * 8;
    int c = t & 63, gi = t >> 6;
    float acc0 = 0.f, acc1 = 0.f;

    for (int chunk = 0; chunk < POOLW/64; chunk++) {
        int m0 = chunk*64;
        __syncthreads();
        for (int idx = t; idx < 64*64; idx += 256)
            ws[idx] = Wl1[(size_t)(m0 + (idx >> 6))*64 + (idx & 63)];
        for (int idx = t; idx < 8*64; idx += 256) {
            int gg = idx >> 6, mm = idx & 63;
            ps[idx] = g_pool[(size_t)(g0 + gg)*POOLW + m0 + mm];
        }
        __syncthreads();
        #pragma unroll
        for (int kk = 0; kk < 64; kk++) {
            float w = ws[kk*64 + c];
            acc0 += ps[gi*64 + kk] * w;
            acc1 += ps[(gi+4)*64 + kk] * w;
        }
    }
    __syncthreads();
    pbuf[gi*64 + c]     = acc0 + bl1[c];
    pbuf[(gi+4)*64 + c] = acc1 + bl1[c];
    __syncthreads();
    int w = t >> 5, lane = t & 31;
    float v = pbuf[w*64 + lane]*Wl2[lane] + pbuf[w*64 + lane + 32]*Wl2[lane + 32];
    #pragma unroll
    for (int o = 16; o; o >>= 1) v += __shfl_xor_sync(0xffffffffu, v, o);
    if (lane == 0) outG[g0 + w] = 1.f / (1.f + expf(-(v + bl2[0])));
}

// ---------------------------------------------------------------------------
extern "C" void kernel_launch(void* const* d_in, const int* in_sizes, int n_in,
                              void* d_out, int out_size) {
    const float *x = 0, *W1l = 0, *W1r = 0, *W2l = 0, *W2r = 0;
    const float *Wl1 = 0, *bl2 = 0;
    const int   *ei = 0;
    int i5760 = 0, i4096 = 0;
    int idx64[8]; int n64 = 0;

    for (int i = 0; i < n_in; i++) {
        int sz = in_sizes[i];
        const float* p = (const float*)d_in[i];
        switch (sz) {
            case 4147200: x   = p; break;                       // [46080,90]
            case 1843200: ei  = (const int*)d_in[i]; break;     // [2,921600]
            case  286720: Wl1 = p; break;                       // [4480,64]
            case    5760: if (i5760++ == 0) W1l = p; else W1r = p; break;
            case    4096: if (i4096++ == 0) W2l = p; else W2r = p; break;
            case      64: if (n64 < 8) idx64[n64++] = i; break; // b1,b2,bl1,Wl2
            case       1: bl2 = p; break;
            default: break;                                     // batch unused
        }
    }
    const float *b1, *b2, *bl1, *Wl2;
    if (n_in > 0 && in_sizes[0] == 5760) {          // alphabetical (W* first)
        Wl2 = (const float*)d_in[idx64[0]];
        b1  = (const float*)d_in[idx64[1]];
        b2  = (const float*)d_in[idx64[2]];
        bl1 = (const float*)d_in[idx64[3]];
    } else {                                        // dict / signature order
        b1  = (const float*)d_in[idx64[0]];
        b2  = (const float*)d_in[idx64[1]];
        bl1 = (const float*)d_in[idx64[2]];
        Wl2 = (const float*)d_in[idx64[3]];
    }

    float* outG = (float*)d_out;
    float* xtp  = (out_size >= G + NTOT*HC) ? (float*)d_out + G : (float*)0;
    int E = 1843200 / 2;

    // (1) zero adjacency + detect edge dtype
    zeroA_kernel<<<2048, 512>>>(ei);
    // (2) edge counts
    edge_kernel<<<(E + 255)/256, 256>>>(ei, E);
    // (3) conv1 fused: projection + aggregation -> g_H1 (+x_train)
    conv_fused<1><<<G, 384>>>(x, W1l, W1r, b1, xtp);
    // (4) conv2 fused: projection + aggregation + sort-pool -> g_pool
    conv_fused<2><<<G, 384>>>((const float*)0, W2l, W2r, b2, (float*)0);
    // (5) MLP head
    final_kernel<<<G/8, 256>>>(Wl1, bl1, Wl2, bl2, outG);
}

// round 14
// speedup vs baseline: 1.6814x; 1.0571x over previous
#include <cuda_runtime.h>
#include <math.h>
#include <stdint.h>

#define G    512
#define NPG  90
#define NTOT (G*NPG)      // 46080
#define FIN  90
#define HC   64
#define KP   70
#define POOLW (KP*HC)     // 4480
#define AW   24           // words per packed A row (96 bytes)

// ---------------- scratch (device globals; referenced ONLY in device code) --
__device__ uint32_t g_Au[G*NPG*AW];  // byte-packed edge counts, 4.4MB
__device__ float    g_pool[G*POOLW]; // sort-pooled features
__device__ int      g_mode;          // 1 = edge data is int64 (odd words zero)

// ---------------- tf32 helpers ----------------------------------------------
__device__ __forceinline__ uint32_t f2tf32(float x) {
    uint32_t r;
    asm("cvt.rna.tf32.f32 %0, %1;" : "=r"(r) : "f"(x));
    return r;
}
__device__ __forceinline__ void split_tf32(float x, uint32_t& hi, uint32_t& lo) {
    hi = f2tf32(x);
    lo = f2tf32(x - __uint_as_float(hi));
}
__device__ __forceinline__ void mma_tf32(float* d, const uint32_t* a,
                                         uint32_t b0, uint32_t b1) {
    asm volatile(
        "mma.sync.aligned.m16n8k8.row.col.f32.tf32.tf32.f32 "
        "{%0,%1,%2,%3},{%4,%5,%6,%7},{%8,%9},{%0,%1,%2,%3};"
        : "+f"(d[0]), "+f"(d[1]), "+f"(d[2]), "+f"(d[3])
        : "r"(a[0]), "r"(a[1]), "r"(a[2]), "r"(a[3]), "r"(b0), "r"(b1));
}

// ---------------- zero packed adjacency + edge dtype detection --------------
__global__ void zeroA_kernel(const int* __restrict__ ei) {
    if (blockIdx.x == 0 && threadIdx.x < 32) {
        int lane = threadIdx.x;
        int nz = 0;
        for (int i = lane; i < 512; i += 32) nz |= ei[2*i + 1];
        unsigned any = __ballot_sync(0xffffffffu, nz != 0);
        if (lane == 0) g_mode = (any == 0);
    }
    int n = G*NPG*AW/4;
    uint4* p = (uint4*)g_Au;
    uint4 z = make_uint4(0u, 0u, 0u, 0u);
    for (int i = blockIdx.x*blockDim.x + threadIdx.x; i < n; i += gridDim.x*blockDim.x)
        p[i] = z;
}

__global__ void edge_kernel(const int* __restrict__ ei, int E) {
    int e = blockIdx.x*blockDim.x + threadIdx.x;
    if (e >= E) return;
    int s, d;
    if (g_mode) { s = ei[2*e]; d = ei[2*(E + e)]; }   // int64 storage
    else        { s = ei[e];   d = ei[E + e];      }  // int32 storage
    if ((unsigned)s >= NTOT || (unsigned)d >= NTOT) return;
    int g  = d / NPG;
    int sl = s - g*NPG;
    int dl = d - g*NPG;
    if ((unsigned)sl >= NPG) return;
    atomicAdd(&g_Au[(size_t)(g*NPG + dl)*AW + (sl >> 2)], 1u << (8*(sl & 3)));
}

// ---------------- MEGA-fused: conv1 + conv2 + sort-pool, 1 block/graph ------
// smem multiplexing:  AX: X1 (B1) -> A tf32 (C1,C2)
//                     pf: P1[0:64] (C1) -> relu(h1)=X2 (B2) -> P2[0:64] (C2)
//                     skp: P1[64:] (C1) -> P2[64:] (C2)
//                     whi/wlo: W1 stages -> W2 stages
__global__ __launch_bounds__(384, 2) void conv_both(const float* __restrict__ X1,
                                                    const float* __restrict__ W1l,
                                                    const float* __restrict__ W1r,
                                                    const float* __restrict__ b1,
                                                    const float* __restrict__ W2l,
                                                    const float* __restrict__ W2r,
                                                    const float* __restrict__ b2,
                                                    float* __restrict__ xtrain) {
    __shared__ uint32_t AX[96*100];
    __shared__ uint32_t whi[16*136];
    __shared__ uint32_t wlo[16*136];
    __shared__ float    pf [96*68];
    __shared__ float    skp[96*68];
    __shared__ float    inv[96];
    __shared__ float    key[96];
    __shared__ int      rrank[96];

    int g = blockIdx.x, t = threadIdx.x;
    int lane = t & 31, w = t >> 5;
    float* Xs = (float*)AX;

    // ---- stage X1 (zero-fill covers pads) ----
    for (int i = t; i < 96*100; i += 384) Xs[i] = 0.f;
    __syncthreads();
    for (int i = t; i < NPG*FIN; i += 384) {
        int r = i / FIN, k = i - r*FIN;
        Xs[r*100 + k] = X1[(size_t)(g*NPG + r)*FIN + k];
    }

    int gid = lane >> 2, tig = lane & 3;
    int wm  = (w >= 6) ? w - 6 : w;
    int ch  = (w >= 6) ? 1 : 0;
    int row0 = wm*16 + gid, row1 = row0 + 8;
    int cbase = ch*64;
    int cb2   = ch*32;

    float acc[8][4];
    #pragma unroll
    for (int i = 0; i < 8; i++)
        #pragma unroll
        for (int j = 0; j < 4; j++) acc[i][j] = 0.f;

    // ================= B1: P1 = X1 @ [W1l|W1r], KD=90, 6 stages ==============
    for (int s = 0; s < 6; s++) {
        int kt = s*16;
        __syncthreads();
        for (int i = t; i < 16*128; i += 384) {
            int kk = i >> 7, c = i & 127;
            int kg = kt + kk;
            float wv = 0.f;
            if (kg < FIN) wv = (c < 64) ? W1l[kg*64 + c] : W1r[kg*64 + (c - 64)];
            uint32_t h, l; split_tf32(wv, h, l);
            whi[kk*136 + c] = h; wlo[kk*136 + c] = l;
        }
        __syncthreads();
        #pragma unroll
        for (int kt2 = 0; kt2 < 16; kt2 += 8) {
            int kA = kt + kt2;
            float a0 = Xs[row0*100 + kA + tig];
            float a1 = Xs[row1*100 + kA + tig];
            float a2 = Xs[row0*100 + kA + tig + 4];
            float a3 = Xs[row1*100 + kA + tig + 4];
            uint32_t ah[4], al[4];
            split_tf32(a0, ah[0], al[0]);
            split_tf32(a1, ah[1], al[1]);
            split_tf32(a2, ah[2], al[2]);
            split_tf32(a3, ah[3], al[3]);
            #pragma unroll
            for (int nt = 0; nt < 8; nt++) {
                int col = cbase + nt*8 + gid;
                uint32_t b0h = whi[(kt2 + tig)*136 + col];
                uint32_t b1h = whi[(kt2 + tig + 4)*136 + col];
                uint32_t b0l = wlo[(kt2 + tig)*136 + col];
                uint32_t b1l = wlo[(kt2 + tig + 4)*136 + col];
                mma_tf32(acc[nt], ah, b0h, b1h);
                mma_tf32(acc[nt], ah, b0l, b1l);
                mma_tf32(acc[nt], al, b0h, b1h);
            }
        }
    }
    // ---- B1 epilogue: P1 -> pf / skp (no reader yet, no pre-sync needed) ----
    {
        float* dst = (ch == 0) ? pf : skp;
        #pragma unroll
        for (int nt = 0; nt < 8; nt++) {
            int c = nt*8 + 2*tig;
            *(float2*)&dst[row0*68 + c] = make_float2(acc[nt][0], acc[nt][1]);
            *(float2*)&dst[row1*68 + c] = make_float2(acc[nt][2], acc[nt][3]);
        }
    }
    __syncthreads();   // pf/skp ready; all B1 reads of AX(X1) done

    // ---- stage A (byte-packed -> tf32, exact) + rowsums via dp4a -----------
    const uint32_t* Ag = g_Au + (size_t)g*NPG*AW;
    {
        int wi = lane;                       // lanes 0..23 active per row
        #pragma unroll
        for (int i2 = 0; i2 < 8; i2++) {
            int r = w*8 + i2;
            uint32_t word = 0;
            if (wi < AW && r < NPG) word = Ag[r*AW + wi];
            if (wi < AW) {
                #pragma unroll
                for (int j = 0; j < 4; j++)
                    AX[r*100 + wi*4 + j] = f2tf32((float)((word >> (8*j)) & 0xFF));
            }
            int psum = __dp4a((int)word, 0x01010101, 0);
            #pragma unroll
            for (int o = 16; o; o >>= 1) psum += __shfl_xor_sync(0xffffffffu, psum, o);
            if (lane == 0) inv[r] = 1.0f / fmaxf((float)psum, 1.0f);
        }
    }
    __syncthreads();

    // ================= C1: H1 = rowmean(A @ P1[:,0:64]) + skp + b1 ===========
    float ac2[4][4];
    #pragma unroll
    for (int i = 0; i < 4; i++)
        #pragma unroll
        for (int j = 0; j < 4; j++) ac2[i][j] = 0.f;

    #pragma unroll
    for (int k8 = 0; k8 < 96; k8 += 8) {
        uint32_t a[4];
        a[0] = AX[row0*100 + k8 + tig];
        a[1] = AX[row1*100 + k8 + tig];
        a[2] = AX[row0*100 + k8 + tig + 4];
        a[3] = AX[row1*100 + k8 + tig + 4];
        #pragma unroll
        for (int nt = 0; nt < 4; nt++) {
            int col = cb2 + nt*8 + gid;
            float b0 = pf[(k8 + tig)*68 + col];
            float b1 = pf[(k8 + tig + 4)*68 + col];
            uint32_t b0h, b0l, b1h, b1l;
            split_tf32(b0, b0h, b0l);
            split_tf32(b1, b1h, b1l);
            mma_tf32(ac2[nt], a, b0h, b1h);
            mma_tf32(ac2[nt], a, b0l, b1l);
        }
    }
    __syncthreads();   // all C1 reads of pf done before overwrite with X2

    // ---- C1 epilogue: h1 -> xtrain (gmem) ; relu(h1) -> pf (=X2) -----------
    {
        float i0 = inv[row0], i1 = inv[row1];
        #pragma unroll
        for (int nt = 0; nt < 4; nt++) {
            int c0 = cb2 + nt*8 + 2*tig;
            float bc0 = __ldg(&b1[c0]), bc1 = __ldg(&b1[c0 + 1]);
            float v00 = ac2[nt][0]*i0 + skp[row0*68 + c0]     + bc0;
            float v01 = ac2[nt][1]*i0 + skp[row0*68 + c0 + 1] + bc1;
            float v10 = ac2[nt][2]*i1 + skp[row1*68 + c0]     + bc0;
            float v11 = ac2[nt][3]*i1 + skp[row1*68 + c0 + 1] + bc1;
            if (xtrain) {
                if (row0 < NPG)
                    *(float2*)&xtrain[(size_t)(g*NPG + row0)*HC + c0] = make_float2(v00, v01);
                if (row1 < NPG)
                    *(float2*)&xtrain[(size_t)(g*NPG + row1)*HC + c0] = make_float2(v10, v11);
            }
            pf[row0*68 + c0]     = fmaxf(v00, 0.f);
            pf[row0*68 + c0 + 1] = fmaxf(v01, 0.f);
            pf[row1*68 + c0]     = fmaxf(v10, 0.f);
            pf[row1*68 + c0 + 1] = fmaxf(v11, 0.f);
        }
    }
    __syncthreads();   // X2 complete

    // ================= B2: P2 = X2 @ [W2l|W2r], KD=64, 4 stages ==============
    #pragma unroll
    for (int i = 0; i < 8; i++)
        #pragma unroll
        for (int j = 0; j < 4; j++) acc[i][j] = 0.f;

    for (int s = 0; s < 4; s++) {
        int kt = s*16;
        __syncthreads();
        for (int i = t; i < 16*128; i += 384) {
            int kk = i >> 7, c = i & 127;
            int kg = kt + kk;
            float wv = (c < 64) ? W2l[kg*64 + c] : W2r[kg*64 + (c - 64)];
            uint32_t h, l; split_tf32(wv, h, l);
            whi[kk*136 + c] = h; wlo[kk*136 + c] = l;
        }
        __syncthreads();
        #pragma unroll
        for (int kt2 = 0; kt2 < 16; kt2 += 8) {
            int kA = kt + kt2;
            float a0 = pf[row0*68 + kA + tig];
            float a1 = pf[row1*68 + kA + tig];
            float a2 = pf[row0*68 + kA + tig + 4];
            float a3 = pf[row1*68 + kA + tig + 4];
            uint32_t ah[4], al[4];
            split_tf32(a0, ah[0], al[0]);
            split_tf32(a1, ah[1], al[1]);
            split_tf32(a2, ah[2], al[2]);
            split_tf32(a3, ah[3], al[3]);
            #pragma unroll
            for (int nt = 0; nt < 8; nt++) {
                int col = cbase + nt*8 + gid;
                uint32_t b0h = whi[(kt2 + tig)*136 + col];
                uint32_t b1h = whi[(kt2 + tig + 4)*136 + col];
                uint32_t b0l = wlo[(kt2 + tig)*136 + col];
                uint32_t b1l = wlo[(kt2 + tig + 4)*136 + col];
                mma_tf32(acc[nt], ah, b0h, b1h);
                mma_tf32(acc[nt], ah, b0l, b1l);
                mma_tf32(acc[nt], al, b0h, b1h);
            }
        }
    }
    __syncthreads();   // all B2 reads of pf(X2) done before overwrite with P2

    // ---- B2 epilogue: P2 -> pf / skp ----
    {
        float* dst = (ch == 0) ? pf : skp;
        #pragma unroll
        for (int nt = 0; nt < 8; nt++) {
            int c = nt*8 + 2*tig;
            *(float2*)&dst[row0*68 + c] = make_float2(acc[nt][0], acc[nt][1]);
            *(float2*)&dst[row1*68 + c] = make_float2(acc[nt][2], acc[nt][3]);
        }
    }
    __syncthreads();

    // ================= C2: H2 = rowmean(A @ P2[:,0:64]) + skp + b2 ===========
    #pragma unroll
    for (int i = 0; i < 4; i++)
        #pragma unroll
        for (int j = 0; j < 4; j++) ac2[i][j] = 0.f;

    #pragma unroll
    for (int k8 = 0; k8 < 96; k8 += 8) {
        uint32_t a[4];
        a[0] = AX[row0*100 + k8 + tig];
        a[1] = AX[row1*100 + k8 + tig];
        a[2] = AX[row0*100 + k8 + tig + 4];
        a[3] = AX[row1*100 + k8 + tig + 4];
        #pragma unroll
        for (int nt = 0; nt < 4; nt++) {
            int col = cb2 + nt*8 + gid;
            float b0 = pf[(k8 + tig)*68 + col];
            float b1 = pf[(k8 + tig + 4)*68 + col];
            uint32_t b0h, b0l, b1h, b1l;
            split_tf32(b0, b0h, b0l);
            split_tf32(b1, b1h, b1l);
            mma_tf32(ac2[nt], a, b0h, b1h);
            mma_tf32(ac2[nt], a, b0l, b1l);
        }
    }

    // ---- C2 epilogue + fused sort-pool ----
    {
        float i0 = inv[row0], i1 = inv[row1];
        #pragma unroll
        for (int nt = 0; nt < 4; nt++) {
            int c0 = cb2 + nt*8 + 2*tig;
            float bc0 = __ldg(&b2[c0]), bc1 = __ldg(&b2[c0 + 1]);
            ac2[nt][0] = ac2[nt][0]*i0 + skp[row0*68 + c0]     + bc0;
            ac2[nt][1] = ac2[nt][1]*i0 + skp[row0*68 + c0 + 1] + bc1;
            ac2[nt][2] = ac2[nt][2]*i1 + skp[row1*68 + c0]     + bc0;
            ac2[nt][3] = ac2[nt][3]*i1 + skp[row1*68 + c0 + 1] + bc1;
        }
    }
    if (ch == 1 && tig == 3) {           // channel 63 = nt3, col 62/63 pair hi
        if (row0 < NPG) key[row0] = ac2[3][1];
        if (row1 < NPG) key[row1] = ac2[3][3];
    }
    __syncthreads();
    if (t < NPG) {
        float v = key[t];
        int rank = 0;
        for (int j = 0; j < NPG; j++) {
            float u = key[j];
            rank += (u > v) || (u == v && j < t);
        }
        rrank[t] = rank;
    }
    __syncthreads();
    {
        int rk0 = (row0 < NPG) ? rrank[row0] : KP;
        int rk1 = (row1 < NPG) ? rrank[row1] : KP;
        #pragma unroll
        for (int nt = 0; nt < 4; nt++) {
            int c0 = cb2 + nt*8 + 2*tig;
            if (rk0 < KP)
                *(float2*)&g_pool[(size_t)g*POOLW + rk0*HC + c0] =
                    make_float2(ac2[nt][0], ac2[nt][1]);
            if (rk1 < KP)
                *(float2*)&g_pool[(size_t)g*POOLW + rk1*HC + c0] =
                    make_float2(ac2[nt][2], ac2[nt][3]);
        }
    }
}

// ---------------- final: pool @ Wl1 + bl1, @ Wl2 + bl2, sigmoid -------------
__global__ __launch_bounds__(256) void final_kernel(const float* __restrict__ Wl1,
                                                    const float* __restrict__ bl1,
                                                    const float* __restrict__ Wl2,
                                                    const float* __restrict__ bl2,
                                                    float* __restrict__ outG) {
    __shared__ float ws[64*64];
    __shared__ float ps[8*64];
    __shared__ float pbuf[8*64];
    int t = threadIdx.x;
    int g0 = blockIdx.x * 8;
    int c = t & 63, gi = t >> 6;
    float acc0 = 0.f, acc1 = 0.f;

    for (int chunk = 0; chunk < POOLW/64; chunk++) {
        int m0 = chunk*64;
        __syncthreads();
        for (int idx = t; idx < 64*64; idx += 256)
            ws[idx] = Wl1[(size_t)(m0 + (idx >> 6))*64 + (idx & 63)];
        for (int idx = t; idx < 8*64; idx += 256) {
            int gg = idx >> 6, mm = idx & 63;
            ps[idx] = g_pool[(size_t)(g0 + gg)*POOLW + m0 + mm];
        }
        __syncthreads();
        #pragma unroll
        for (int kk = 0; kk < 64; kk++) {
            float w = ws[kk*64 + c];
            acc0 += ps[gi*64 + kk] * w;
            acc1 += ps[(gi+4)*64 + kk] * w;
        }
    }
    __syncthreads();
    pbuf[gi*64 + c]     = acc0 + bl1[c];
    pbuf[(gi+4)*64 + c] = acc1 + bl1[c];
    __syncthreads();
    int w = t >> 5, lane = t & 31;
    float v = pbuf[w*64 + lane]*Wl2[lane] + pbuf[w*64 + lane + 32]*Wl2[lane + 32];
    #pragma unroll
    for (int o = 16; o; o >>= 1) v += __shfl_xor_sync(0xffffffffu, v, o);
    if (lane == 0) outG[g0 + w] = 1.f / (1.f + expf(-(v + bl2[0])));
}

// ---------------------------------------------------------------------------
extern "C" void kernel_launch(void* const* d_in, const int* in_sizes, int n_in,
                              void* d_out, int out_size) {
    const float *x = 0, *W1l = 0, *W1r = 0, *W2l = 0, *W2r = 0;
    const float *Wl1 = 0, *bl2 = 0;
    const int   *ei = 0;
    int i5760 = 0, i4096 = 0;
    int idx64[8]; int n64 = 0;

    for (int i = 0; i < n_in; i++) {
        int sz = in_sizes[i];
        const float* p = (const float*)d_in[i];
        switch (sz) {
            case 4147200: x   = p; break;                       // [46080,90]
            case 1843200: ei  = (const int*)d_in[i]; break;     // [2,921600]
            case  286720: Wl1 = p; break;                       // [4480,64]
            case    5760: if (i5760++ == 0) W1l = p; else W1r = p; break;
            case    4096: if (i4096++ == 0) W2l = p; else W2r = p; break;
            case      64: if (n64 < 8) idx64[n64++] = i; break; // b1,b2,bl1,Wl2
            case       1: bl2 = p; break;
            default: break;                                     // batch unused
        }
    }
    const float *b1, *b2, *bl1, *Wl2;
    if (n_in > 0 && in_sizes[0] == 5760) {          // alphabetical (W* first)
        Wl2 = (const float*)d_in[idx64[0]];
        b1  = (const float*)d_in[idx64[1]];
        b2  = (const float*)d_in[idx64[2]];
        bl1 = (const float*)d_in[idx64[3]];
    } else {                                        // dict / signature order
        b1  = (const float*)d_in[idx64[0]];
        b2  = (const float*)d_in[idx64[1]];
        bl1 = (const float*)d_in[idx64[2]];
        Wl2 = (const float*)d_in[idx64[3]];
    }

    float* outG = (float*)d_out;
    float* xtp  = (out_size >= G + NTOT*HC) ? (float*)d_out + G : (float*)0;
    int E = 1843200 / 2;

    // (1) zero packed adjacency + detect edge dtype
    zeroA_kernel<<<540, 512>>>(ei);
    // (2) edge counts (byte-packed atomics)
    edge_kernel<<<(E + 255)/256, 256>>>(ei, E);
    // (3) conv1 + conv2 + sort-pool mega-fused
    conv_both<<<G, 384>>>(x, W1l, W1r, b1, W2l, W2r, b2, xtp);
    // (4) MLP head  [<- ncu capture slot]
    final_kernel<<<G/8, 256>>>(Wl1, bl1, Wl2, bl2, outG);
}

// round 15
// speedup vs baseline: 3.1303x; 1.8618x over previous
#include <cuda_runtime.h>
#include <math.h>
#include <stdint.h>

#define G    512
#define NPG  90
#define NTOT (G*NPG)      // 46080
#define FIN  90
#define HC   64
#define KP   70
#define POOLW (KP*HC)     // 4480
#define AW   24           // words per packed A row (96 bytes)

// ---------------- scratch (device globals; referenced ONLY in device code) --
__device__ uint32_t g_Au[G*NPG*AW];  // byte-packed edge counts, 4.4MB
__device__ float    g_pool[G*POOLW]; // sort-pooled features
__device__ float    g_h512[G*HC];    // head partials (pool @ Wl1)
__device__ int      g_mode;          // 1 = edge data is int64 (odd words zero)

// ---------------- tf32 helpers ----------------------------------------------
__device__ __forceinline__ uint32_t f2tf32(float x) {
    uint32_t r;
    asm("cvt.rna.tf32.f32 %0, %1;" : "=r"(r) : "f"(x));
    return r;
}
__device__ __forceinline__ void split_tf32(float x, uint32_t& hi, uint32_t& lo) {
    hi = f2tf32(x);
    lo = f2tf32(x - __uint_as_float(hi));
}
__device__ __forceinline__ void mma_tf32(float* d, const uint32_t* a,
                                         uint32_t b0, uint32_t b1) {
    asm volatile(
        "mma.sync.aligned.m16n8k8.row.col.f32.tf32.tf32.f32 "
        "{%0,%1,%2,%3},{%4,%5,%6,%7},{%8,%9},{%0,%1,%2,%3};"
        : "+f"(d[0]), "+f"(d[1]), "+f"(d[2]), "+f"(d[3])
        : "r"(a[0]), "r"(a[1]), "r"(a[2]), "r"(a[3]), "r"(b0), "r"(b1));
}

// ---------------- zero packed adjacency + head partials + dtype detect ------
__global__ void zeroA_kernel(const int* __restrict__ ei) {
    if (blockIdx.x == 0 && threadIdx.x < 32) {
        int lane = threadIdx.x;
        int nz = 0;
        for (int i = lane; i < 512; i += 32) nz |= ei[2*i + 1];
        unsigned any = __ballot_sync(0xffffffffu, nz != 0);
        if (lane == 0) g_mode = (any == 0);
    }
    int n = G*NPG*AW/4;
    uint4* p = (uint4*)g_Au;
    uint4 z = make_uint4(0u, 0u, 0u, 0u);
    for (int i = blockIdx.x*blockDim.x + threadIdx.x; i < n; i += gridDim.x*blockDim.x)
        p[i] = z;
    int nh = G*HC/4;
    float4* q = (float4*)g_h512;
    float4 zf = make_float4(0.f, 0.f, 0.f, 0.f);
    for (int i = blockIdx.x*blockDim.x + threadIdx.x; i < nh; i += gridDim.x*blockDim.x)
        q[i] = zf;
}

__global__ void edge_kernel(const int* __restrict__ ei, int E) {
    int e = blockIdx.x*blockDim.x + threadIdx.x;
    if (e >= E) return;
    int s, d;
    if (g_mode) { s = ei[2*e]; d = ei[2*(E + e)]; }   // int64 storage
    else        { s = ei[e];   d = ei[E + e];      }  // int32 storage
    if ((unsigned)s >= NTOT || (unsigned)d >= NTOT) return;
    int g  = d / NPG;
    int sl = s - g*NPG;
    int dl = d - g*NPG;
    if ((unsigned)sl >= NPG) return;
    atomicAdd(&g_Au[(size_t)(g*NPG + dl)*AW + (sl >> 2)], 1u << (8*(sl & 3)));
}

// ---------------- MEGA-fused: conv1 + conv2 + sort-pool, 1 block/graph ------
__global__ __launch_bounds__(384, 2) void conv_both(const float* __restrict__ X1,
                                                    const float* __restrict__ W1l,
                                                    const float* __restrict__ W1r,
                                                    const float* __restrict__ b1,
                                                    const float* __restrict__ W2l,
                                                    const float* __restrict__ W2r,
                                                    const float* __restrict__ b2,
                                                    float* __restrict__ xtrain) {
    __shared__ uint32_t AX[96*100];
    __shared__ uint32_t whi[16*136];
    __shared__ uint32_t wlo[16*136];
    __shared__ float    pf [96*68];
    __shared__ float    skp[96*68];
    __shared__ float    inv[96];
    __shared__ float    key[96];
    __shared__ int      rrank[96];

    int g = blockIdx.x, t = threadIdx.x;
    int lane = t & 31, w = t >> 5;
    float* Xs = (float*)AX;

    // ---- stage X1 (zero-fill covers pads) ----
    for (int i = t; i < 96*100; i += 384) Xs[i] = 0.f;
    __syncthreads();
    for (int i = t; i < NPG*FIN; i += 384) {
        int r = i / FIN, k = i - r*FIN;
        Xs[r*100 + k] = X1[(size_t)(g*NPG + r)*FIN + k];
    }

    int gid = lane >> 2, tig = lane & 3;
    int wm  = (w >= 6) ? w - 6 : w;
    int ch  = (w >= 6) ? 1 : 0;
    int row0 = wm*16 + gid, row1 = row0 + 8;
    int cbase = ch*64;
    int cb2   = ch*32;

    float acc[8][4];
    #pragma unroll
    for (int i = 0; i < 8; i++)
        #pragma unroll
        for (int j = 0; j < 4; j++) acc[i][j] = 0.f;

    // ================= B1: P1 = X1 @ [W1l|W1r], KD=90, 6 stages ==============
    for (int s = 0; s < 6; s++) {
        int kt = s*16;
        __syncthreads();
        for (int i = t; i < 16*128; i += 384) {
            int kk = i >> 7, c = i & 127;
            int kg = kt + kk;
            float wv = 0.f;
            if (kg < FIN) wv = (c < 64) ? W1l[kg*64 + c] : W1r[kg*64 + (c - 64)];
            uint32_t h, l; split_tf32(wv, h, l);
            whi[kk*136 + c] = h; wlo[kk*136 + c] = l;
        }
        __syncthreads();
        #pragma unroll
        for (int kt2 = 0; kt2 < 16; kt2 += 8) {
            int kA = kt + kt2;
            float a0 = Xs[row0*100 + kA + tig];
            float a1 = Xs[row1*100 + kA + tig];
            float a2 = Xs[row0*100 + kA + tig + 4];
            float a3 = Xs[row1*100 + kA + tig + 4];
            uint32_t ah[4], al[4];
            split_tf32(a0, ah[0], al[0]);
            split_tf32(a1, ah[1], al[1]);
            split_tf32(a2, ah[2], al[2]);
            split_tf32(a3, ah[3], al[3]);
            #pragma unroll
            for (int nt = 0; nt < 8; nt++) {
                int col = cbase + nt*8 + gid;
                uint32_t b0h = whi[(kt2 + tig)*136 + col];
                uint32_t b1h = whi[(kt2 + tig + 4)*136 + col];
                uint32_t b0l = wlo[(kt2 + tig)*136 + col];
                uint32_t b1l = wlo[(kt2 + tig + 4)*136 + col];
                mma_tf32(acc[nt], ah, b0h, b1h);
                mma_tf32(acc[nt], ah, b0l, b1l);
                mma_tf32(acc[nt], al, b0h, b1h);
            }
        }
    }
    // ---- B1 epilogue: P1 -> pf / skp ----
    {
        float* dst = (ch == 0) ? pf : skp;
        #pragma unroll
        for (int nt = 0; nt < 8; nt++) {
            int c = nt*8 + 2*tig;
            *(float2*)&dst[row0*68 + c] = make_float2(acc[nt][0], acc[nt][1]);
            *(float2*)&dst[row1*68 + c] = make_float2(acc[nt][2], acc[nt][3]);
        }
    }
    __syncthreads();   // pf/skp ready; all B1 reads of AX(X1) done

    // ---- stage A (byte-packed -> tf32, exact) + rowsums via dp4a -----------
    const uint32_t* Ag = g_Au + (size_t)g*NPG*AW;
    {
        int wi = lane;
        #pragma unroll
        for (int i2 = 0; i2 < 8; i2++) {
            int r = w*8 + i2;
            uint32_t word = 0;
            if (wi < AW && r < NPG) word = Ag[r*AW + wi];
            if (wi < AW) {
                #pragma unroll
                for (int j = 0; j < 4; j++)
                    AX[r*100 + wi*4 + j] = f2tf32((float)((word >> (8*j)) & 0xFF));
            }
            int psum = __dp4a((int)word, 0x01010101, 0);
            #pragma unroll
            for (int o = 16; o; o >>= 1) psum += __shfl_xor_sync(0xffffffffu, psum, o);
            if (lane == 0) inv[r] = 1.0f / fmaxf((float)psum, 1.0f);
        }
    }
    __syncthreads();

    // ================= C1: H1 = rowmean(A @ P1[:,0:64]) + skp + b1 ===========
    float ac2[4][4];
    #pragma unroll
    for (int i = 0; i < 4; i++)
        #pragma unroll
        for (int j = 0; j < 4; j++) ac2[i][j] = 0.f;

    #pragma unroll
    for (int k8 = 0; k8 < 96; k8 += 8) {
        uint32_t a[4];
        a[0] = AX[row0*100 + k8 + tig];
        a[1] = AX[row1*100 + k8 + tig];
        a[2] = AX[row0*100 + k8 + tig + 4];
        a[3] = AX[row1*100 + k8 + tig + 4];
        #pragma unroll
        for (int nt = 0; nt < 4; nt++) {
            int col = cb2 + nt*8 + gid;
            float b0 = pf[(k8 + tig)*68 + col];
            float b1 = pf[(k8 + tig + 4)*68 + col];
            uint32_t b0h, b0l, b1h, b1l;
            split_tf32(b0, b0h, b0l);
            split_tf32(b1, b1h, b1l);
            mma_tf32(ac2[nt], a, b0h, b1h);
            mma_tf32(ac2[nt], a, b0l, b1l);
        }
    }
    __syncthreads();   // all C1 reads of pf done before overwrite with X2

    // ---- C1 epilogue: h1 -> xtrain (gmem) ; relu(h1) -> pf (=X2) -----------
    {
        float i0 = inv[row0], i1 = inv[row1];
        #pragma unroll
        for (int nt = 0; nt < 4; nt++) {
            int c0 = cb2 + nt*8 + 2*tig;
            float bc0 = __ldg(&b1[c0]), bc1 = __ldg(&b1[c0 + 1]);
            float v00 = ac2[nt][0]*i0 + skp[row0*68 + c0]     + bc0;
            float v01 = ac2[nt][1]*i0 + skp[row0*68 + c0 + 1] + bc1;
            float v10 = ac2[nt][2]*i1 + skp[row1*68 + c0]     + bc0;
            float v11 = ac2[nt][3]*i1 + skp[row1*68 + c0 + 1] + bc1;
            if (xtrain) {
                if (row0 < NPG)
                    *(float2*)&xtrain[(size_t)(g*NPG + row0)*HC + c0] = make_float2(v00, v01);
                if (row1 < NPG)
                    *(float2*)&xtrain[(size_t)(g*NPG + row1)*HC + c0] = make_float2(v10, v11);
            }
            pf[row0*68 + c0]     = fmaxf(v00, 0.f);
            pf[row0*68 + c0 + 1] = fmaxf(v01, 0.f);
            pf[row1*68 + c0]     = fmaxf(v10, 0.f);
            pf[row1*68 + c0 + 1] = fmaxf(v11, 0.f);
        }
    }
    __syncthreads();   // X2 complete

    // ================= B2: P2 = X2 @ [W2l|W2r], KD=64, 4 stages ==============
    #pragma unroll
    for (int i = 0; i < 8; i++)
        #pragma unroll
        for (int j = 0; j < 4; j++) acc[i][j] = 0.f;

    for (int s = 0; s < 4; s++) {
        int kt = s*16;
        __syncthreads();
        for (int i = t; i < 16*128; i += 384) {
            int kk = i >> 7, c = i & 127;
            int kg = kt + kk;
            float wv = (c < 64) ? W2l[kg*64 + c] : W2r[kg*64 + (c - 64)];
            uint32_t h, l; split_tf32(wv, h, l);
            whi[kk*136 + c] = h; wlo[kk*136 + c] = l;
        }
        __syncthreads();
        #pragma unroll
        for (int kt2 = 0; kt2 < 16; kt2 += 8) {
            int kA = kt + kt2;
            float a0 = pf[row0*68 + kA + tig];
            float a1 = pf[row1*68 + kA + tig];
            float a2 = pf[row0*68 + kA + tig + 4];
            float a3 = pf[row1*68 + kA + tig + 4];
            uint32_t ah[4], al[4];
            split_tf32(a0, ah[0], al[0]);
            split_tf32(a1, ah[1], al[1]);
            split_tf32(a2, ah[2], al[2]);
            split_tf32(a3, ah[3], al[3]);
            #pragma unroll
            for (int nt = 0; nt < 8; nt++) {
                int col = cbase + nt*8 + gid;
                uint32_t b0h = whi[(kt2 + tig)*136 + col];
                uint32_t b1h = whi[(kt2 + tig + 4)*136 + col];
                uint32_t b0l = wlo[(kt2 + tig)*136 + col];
                uint32_t b1l = wlo[(kt2 + tig + 4)*136 + col];
                mma_tf32(acc[nt], ah, b0h, b1h);
                mma_tf32(acc[nt], ah, b0l, b1l);
                mma_tf32(acc[nt], al, b0h, b1h);
            }
        }
    }
    __syncthreads();   // all B2 reads of pf(X2) done before overwrite with P2

    // ---- B2 epilogue: P2 -> pf / skp ----
    {
        float* dst = (ch == 0) ? pf : skp;
        #pragma unroll
        for (int nt = 0; nt < 8; nt++) {
            int c = nt*8 + 2*tig;
            *(float2*)&dst[row0*68 + c] = make_float2(acc[nt][0], acc[nt][1]);
            *(float2*)&dst[row1*68 + c] = make_float2(acc[nt][2], acc[nt][3]);
        }
    }
    __syncthreads();

    // ================= C2: H2 = rowmean(A @ P2[:,0:64]) + skp + b2 ===========
    #pragma unroll
    for (int i = 0; i < 4; i++)
        #pragma unroll
        for (int j = 0; j < 4; j++) ac2[i][j] = 0.f;

    #pragma unroll
    for (int k8 = 0; k8 < 96; k8 += 8) {
        uint32_t a[4];
        a[0] = AX[row0*100 + k8 + tig];
        a[1] = AX[row1*100 + k8 + tig];
        a[2] = AX[row0*100 + k8 + tig + 4];
        a[3] = AX[row1*100 + k8 + tig + 4];
        #pragma unroll
        for (int nt = 0; nt < 4; nt++) {
            int col = cb2 + nt*8 + gid;
            float b0 = pf[(k8 + tig)*68 + col];
            float b1 = pf[(k8 + tig + 4)*68 + col];
            uint32_t b0h, b0l, b1h, b1l;
            split_tf32(b0, b0h, b0l);
            split_tf32(b1, b1h, b1l);
            mma_tf32(ac2[nt], a, b0h, b1h);
            mma_tf32(ac2[nt], a, b0l, b1l);
        }
    }

    // ---- C2 epilogue + fused sort-pool ----
    {
        float i0 = inv[row0], i1 = inv[row1];
        #pragma unroll
        for (int nt = 0; nt < 4; nt++) {
            int c0 = cb2 + nt*8 + 2*tig;
            float bc0 = __ldg(&b2[c0]), bc1 = __ldg(&b2[c0 + 1]);
            ac2[nt][0] = ac2[nt][0]*i0 + skp[row0*68 + c0]     + bc0;
            ac2[nt][1] = ac2[nt][1]*i0 + skp[row0*68 + c0 + 1] + bc1;
            ac2[nt][2] = ac2[nt][2]*i1 + skp[row1*68 + c0]     + bc0;
            ac2[nt][3] = ac2[nt][3]*i1 + skp[row1*68 + c0 + 1] + bc1;
        }
    }
    if (ch == 1 && tig == 3) {           // channel 63
        if (row0 < NPG) key[row0] = ac2[3][1];
        if (row1 < NPG) key[row1] = ac2[3][3];
    }
    __syncthreads();
    if (t < NPG) {
        float v = key[t];
        int rank = 0;
        for (int j = 0; j < NPG; j++) {
            float u = key[j];
            rank += (u > v) || (u == v && j < t);
        }
        rrank[t] = rank;
    }
    __syncthreads();
    {
        int rk0 = (row0 < NPG) ? rrank[row0] : KP;
        int rk1 = (row1 < NPG) ? rrank[row1] : KP;
        #pragma unroll
        for (int nt = 0; nt < 4; nt++) {
            int c0 = cb2 + nt*8 + 2*tig;
            if (rk0 < KP)
                *(float2*)&g_pool[(size_t)g*POOLW + rk0*HC + c0] =
                    make_float2(ac2[nt][0], ac2[nt][1]);
            if (rk1 < KP)
                *(float2*)&g_pool[(size_t)g*POOLW + rk1*HC + c0] =
                    make_float2(ac2[nt][2], ac2[nt][3]);
        }
    }
}

// ---------------- head1: partial pool @ Wl1 -> g_h512 (atomic) ---------------
// grid = 8 graph-tiles x 70 k-chunks = 560 blocks; block = 64 graphs x 64 cols
// x 64-k partial. Thread: c = t&63, gq = t>>6 handles graphs gq+4i (16 each).
__global__ __launch_bounds__(256) void head1(const float* __restrict__ Wl1) {
    __shared__ float ws[64*64];      // Wl1 chunk [k][c] (contiguous slab)
    __shared__ float ps[64*65];      // pool tile [graph][k], pitch 65
    int bt = blockIdx.x;
    int gt = bt & 7;                 // graph tile (64 graphs)
    int chunk = bt >> 3;             // k-chunk 0..69
    int t = threadIdx.x;
    int m0 = chunk*64;

    for (int i = t; i < 4096; i += 256)
        ws[i] = Wl1[(size_t)m0*64 + i];          // rows m0..m0+63 contiguous
    for (int i = t; i < 4096; i += 256) {
        int gg = i >> 6, kk = i & 63;
        ps[gg*65 + kk] = g_pool[(size_t)(gt*64 + gg)*POOLW + m0 + kk];
    }
    __syncthreads();

    int c = t & 63, gq = t >> 6;
    float acc[16];
    #pragma unroll
    for (int i = 0; i < 16; i++) acc[i] = 0.f;

    for (int kk = 0; kk < 64; kk++) {
        float w = ws[kk*64 + c];
        #pragma unroll
        for (int i = 0; i < 16; i++)
            acc[i] += ps[(gq + i*4)*65 + kk] * w;    // broadcast LDS
    }
    #pragma unroll
    for (int i = 0; i < 16; i++)
        atomicAdd(&g_h512[(gt*64 + gq + i*4)*HC + c], acc[i]);
}

// ---------------- head2: (h + bl1) . Wl2 + bl2 -> sigmoid --------------------
__global__ __launch_bounds__(256) void head2(const float* __restrict__ bl1,
                                             const float* __restrict__ Wl2,
                                             const float* __restrict__ bl2,
                                             float* __restrict__ outG) {
    int g = blockIdx.x*8 + (threadIdx.x >> 5);
    int lane = threadIdx.x & 31;
    float v = (g_h512[g*HC + lane]      + bl1[lane])      * Wl2[lane]
            + (g_h512[g*HC + lane + 32] + bl1[lane + 32]) * Wl2[lane + 32];
    #pragma unroll
    for (int o = 16; o; o >>= 1) v += __shfl_xor_sync(0xffffffffu, v, o);
    if (lane == 0) outG[g] = 1.f / (1.f + expf(-(v + bl2[0])));
}

// ---------------------------------------------------------------------------
extern "C" void kernel_launch(void* const* d_in, const int* in_sizes, int n_in,
                              void* d_out, int out_size) {
    const float *x = 0, *W1l = 0, *W1r = 0, *W2l = 0, *W2r = 0;
    const float *Wl1 = 0, *bl2 = 0;
    const int   *ei = 0;
    int i5760 = 0, i4096 = 0;
    int idx64[8]; int n64 = 0;

    for (int i = 0; i < n_in; i++) {
        int sz = in_sizes[i];
        const float* p = (const float*)d_in[i];
        switch (sz) {
            case 4147200: x   = p; break;                       // [46080,90]
            case 1843200: ei  = (const int*)d_in[i]; break;     // [2,921600]
            case  286720: Wl1 = p; break;                       // [4480,64]
            case    5760: if (i5760++ == 0) W1l = p; else W1r = p; break;
            case    4096: if (i4096++ == 0) W2l = p; else W2r = p; break;
            case      64: if (n64 < 8) idx64[n64++] = i; break; // b1,b2,bl1,Wl2
            case       1: bl2 = p; break;
            default: break;                                     // batch unused
        }
    }
    const float *b1, *b2, *bl1, *Wl2;
    if (n_in > 0 && in_sizes[0] == 5760) {          // alphabetical (W* first)
        Wl2 = (const float*)d_in[idx64[0]];
        b1  = (const float*)d_in[idx64[1]];
        b2  = (const float*)d_in[idx64[2]];
        bl1 = (const float*)d_in[idx64[3]];
    } else {                                        // dict / signature order
        b1  = (const float*)d_in[idx64[0]];
        b2  = (const float*)d_in[idx64[1]];
        bl1 = (const float*)d_in[idx64[2]];
        Wl2 = (const float*)d_in[idx64[3]];
    }

    float* outG = (float*)d_out;
    float* xtp  = (out_size >= G + NTOT*HC) ? (float*)d_out + G : (float*)0;
    int E = 1843200 / 2;

    // (1) zero packed adjacency + head partials + detect edge dtype
    zeroA_kernel<<<540, 512>>>(ei);
    // (2) edge counts (byte-packed atomics)
    edge_kernel<<<(E + 255)/256, 256>>>(ei, E);
    // (3) conv1 + conv2 + sort-pool mega-fused
    conv_both<<<G, 384>>>(x, W1l, W1r, b1, W2l, W2r, b2, xtp);
    // (4) head GEMM partials, 560 blocks  [<- ncu capture slot]
    head1<<<560, 256>>>(Wl1);
    // (5) head reduction + sigmoid
    head2<<<G/8, 256>>>(bl1, Wl2, bl2, outG);
}

// round 16
// speedup vs baseline: 3.2920x; 1.0517x over previous
#include <cuda_runtime.h>
#include <math.h>
#include <stdint.h>

#define G    512
#define NPG  90
#define NTOT (G*NPG)      // 46080
#define FIN  90
#define HC   64
#define KP   70
#define POOLW (KP*HC)     // 4480
#define AW   24           // words per packed A row (96 bytes)

// ---------------- scratch (device globals; referenced ONLY in device code) --
__device__ uint32_t g_Au[G*NPG*AW];  // byte-packed edge counts, 4.4MB
__device__ float    g_pool[G*POOLW]; // sort-pooled features
__device__ float    g_h512[G*HC];    // head partials (pool @ Wl1)
__device__ int      g_mode;          // 1 = edge data is int64 (odd words zero)

// ---------------- tf32 helpers ----------------------------------------------
__device__ __forceinline__ uint32_t f2tf32(float x) {
    uint32_t r;
    asm("cvt.rna.tf32.f32 %0, %1;" : "=r"(r) : "f"(x));
    return r;
}
__device__ __forceinline__ void split_tf32(float x, uint32_t& hi, uint32_t& lo) {
    hi = f2tf32(x);
    lo = f2tf32(x - __uint_as_float(hi));
}
__device__ __forceinline__ void mma_tf32(float* d, const uint32_t* a,
                                         uint32_t b0, uint32_t b1) {
    asm volatile(
        "mma.sync.aligned.m16n8k8.row.col.f32.tf32.tf32.f32 "
        "{%0,%1,%2,%3},{%4,%5,%6,%7},{%8,%9},{%0,%1,%2,%3};"
        : "+f"(d[0]), "+f"(d[1]), "+f"(d[2]), "+f"(d[3])
        : "r"(a[0]), "r"(a[1]), "r"(a[2]), "r"(a[3]), "r"(b0), "r"(b1));
}

// ---------------- zero packed adjacency + head partials + dtype detect ------
__global__ void zeroA_kernel(const int* __restrict__ ei) {
    if (blockIdx.x == 0 && threadIdx.x < 32) {
        int lane = threadIdx.x;
        int nz = 0;
        for (int i = lane; i < 512; i += 32) nz |= ei[2*i + 1];
        unsigned any = __ballot_sync(0xffffffffu, nz != 0);
        if (lane == 0) g_mode = (any == 0);
    }
    int n = G*NPG*AW/4;
    uint4* p = (uint4*)g_Au;
    uint4 z = make_uint4(0u, 0u, 0u, 0u);
    for (int i = blockIdx.x*blockDim.x + threadIdx.x; i < n; i += gridDim.x*blockDim.x)
        p[i] = z;
    int nh = G*HC/4;
    float4* q = (float4*)g_h512;
    float4 zf = make_float4(0.f, 0.f, 0.f, 0.f);
    for (int i = blockIdx.x*blockDim.x + threadIdx.x; i < nh; i += gridDim.x*blockDim.x)
        q[i] = zf;
}

// ---------------- edge counts: 2 edges per thread ----------------------------
__global__ void edge_kernel(const int* __restrict__ ei, int E) {
    int e0 = (blockIdx.x*blockDim.x + threadIdx.x)*2;
    if (e0 >= E) return;
    int mode = g_mode;
    #pragma unroll
    for (int j = 0; j < 2; j++) {
        int e = e0 + j;
        if (e >= E) break;
        int s, d;
        if (mode) { s = ei[2*e]; d = ei[2*(E + e)]; }   // int64 storage
        else      { s = ei[e];   d = ei[E + e];      }  // int32 storage
        if ((unsigned)s >= NTOT || (unsigned)d >= NTOT) continue;
        int g  = d / NPG;
        int sl = s - g*NPG;
        int dl = d - g*NPG;
        if ((unsigned)sl >= NPG) continue;
        atomicAdd(&g_Au[(size_t)(g*NPG + dl)*AW + (sl >> 2)], 1u << (8*(sl & 3)));
    }
}

// ---------------- MEGA-fused: conv1 + conv2 + sort-pool, 1 block/graph ------
__global__ __launch_bounds__(384, 2) void conv_both(const float* __restrict__ X1,
                                                    const float* __restrict__ W1l,
                                                    const float* __restrict__ W1r,
                                                    const float* __restrict__ b1,
                                                    const float* __restrict__ W2l,
                                                    const float* __restrict__ W2r,
                                                    const float* __restrict__ b2,
                                                    float* __restrict__ xtrain) {
    __shared__ uint32_t AX[96*100];
    __shared__ uint32_t whi[16*136];
    __shared__ uint32_t wlo[16*136];
    __shared__ float    pf [96*68];
    __shared__ float    skp[96*68];
    __shared__ float    inv[96];
    __shared__ float    key[96];
    __shared__ int      rrank[96];

    int g = blockIdx.x, t = threadIdx.x;
    int lane = t & 31, w = t >> 5;
    float* Xs = (float*)AX;

    // ---- stage X1: zero ONLY pad regions (disjoint from data writes) ----
    for (int i = t; i < 96*6; i += 384) {            // k = 90..95, all rows
        int r = i / 6, k = 90 + (i - (i/6)*6);
        Xs[r*100 + k] = 0.f;
    }
    for (int i = t; i < 6*90; i += 384) {            // rows 90..95, k = 0..89
        int r = 90 + i / 90, k = i - (i/90)*90;
        Xs[r*100 + k] = 0.f;
    }
    for (int i = t; i < NPG*FIN; i += 384) {
        int r = i / FIN, k = i - (i/FIN)*FIN;
        Xs[r*100 + k] = X1[(size_t)(g*NPG + r)*FIN + k];
    }

    int gid = lane >> 2, tig = lane & 3;
    int wm  = (w >= 6) ? w - 6 : w;
    int ch  = (w >= 6) ? 1 : 0;
    int row0 = wm*16 + gid, row1 = row0 + 8;
    int cbase = ch*64;
    int cb2   = ch*32;

    float acc[8][4];
    #pragma unroll
    for (int i = 0; i < 8; i++)
        #pragma unroll
        for (int j = 0; j < 4; j++) acc[i][j] = 0.f;

    // ================= B1: P1 = X1 @ [W1l|W1r], KD=90, 6 stages ==============
    for (int s = 0; s < 6; s++) {
        int kt = s*16;
        __syncthreads();
        for (int i = t; i < 16*128; i += 384) {
            int kk = i >> 7, c = i & 127;
            int kg = kt + kk;
            float wv = 0.f;
            if (kg < FIN) wv = (c < 64) ? W1l[kg*64 + c] : W1r[kg*64 + (c - 64)];
            uint32_t h, l; split_tf32(wv, h, l);
            whi[kk*136 + c] = h; wlo[kk*136 + c] = l;
        }
        __syncthreads();
        #pragma unroll
        for (int kt2 = 0; kt2 < 16; kt2 += 8) {
            int kA = kt + kt2;
            float a0 = Xs[row0*100 + kA + tig];
            float a1 = Xs[row1*100 + kA + tig];
            float a2 = Xs[row0*100 + kA + tig + 4];
            float a3 = Xs[row1*100 + kA + tig + 4];
            uint32_t ah[4], al[4];
            split_tf32(a0, ah[0], al[0]);
            split_tf32(a1, ah[1], al[1]);
            split_tf32(a2, ah[2], al[2]);
            split_tf32(a3, ah[3], al[3]);
            #pragma unroll
            for (int nt = 0; nt < 8; nt++) {
                int col = cbase + nt*8 + gid;
                uint32_t b0h = whi[(kt2 + tig)*136 + col];
                uint32_t b1h = whi[(kt2 + tig + 4)*136 + col];
                uint32_t b0l = wlo[(kt2 + tig)*136 + col];
                uint32_t b1l = wlo[(kt2 + tig + 4)*136 + col];
                mma_tf32(acc[nt], ah, b0h, b1h);
                mma_tf32(acc[nt], ah, b0l, b1l);
                mma_tf32(acc[nt], al, b0h, b1h);
            }
        }
    }
    // ---- B1 epilogue: P1 -> pf / skp ----
    {
        float* dst = (ch == 0) ? pf : skp;
        #pragma unroll
        for (int nt = 0; nt < 8; nt++) {
            int c = nt*8 + 2*tig;
            *(float2*)&dst[row0*68 + c] = make_float2(acc[nt][0], acc[nt][1]);
            *(float2*)&dst[row1*68 + c] = make_float2(acc[nt][2], acc[nt][3]);
        }
    }
    __syncthreads();   // pf/skp ready; all B1 reads of AX(X1) done

    // ---- stage A (byte-packed -> tf32, exact) + rowsums via dp4a -----------
    const uint32_t* Ag = g_Au + (size_t)g*NPG*AW;
    {
        int wi = lane;
        #pragma unroll
        for (int i2 = 0; i2 < 8; i2++) {
            int r = w*8 + i2;
            uint32_t word = 0;
            if (wi < AW && r < NPG) word = Ag[r*AW + wi];
            if (wi < AW) {
                #pragma unroll
                for (int j = 0; j < 4; j++)
                    AX[r*100 + wi*4 + j] = f2tf32((float)((word >> (8*j)) & 0xFF));
            }
            int psum = __dp4a((int)word, 0x01010101, 0);
            #pragma unroll
            for (int o = 16; o; o >>= 1) psum += __shfl_xor_sync(0xffffffffu, psum, o);
            if (lane == 0) inv[r] = 1.0f / fmaxf((float)psum, 1.0f);
        }
    }
    __syncthreads();

    // ================= C1: H1 = rowmean(A @ P1[:,0:64]) + skp + b1 ===========
    float ac2[4][4];
    #pragma unroll
    for (int i = 0; i < 4; i++)
        #pragma unroll
        for (int j = 0; j < 4; j++) ac2[i][j] = 0.f;

    #pragma unroll
    for (int k8 = 0; k8 < 96; k8 += 8) {
        uint32_t a[4];
        a[0] = AX[row0*100 + k8 + tig];
        a[1] = AX[row1*100 + k8 + tig];
        a[2] = AX[row0*100 + k8 + tig + 4];
        a[3] = AX[row1*100 + k8 + tig + 4];
        #pragma unroll
        for (int nt = 0; nt < 4; nt++) {
            int col = cb2 + nt*8 + gid;
            float b0 = pf[(k8 + tig)*68 + col];
            float b1 = pf[(k8 + tig + 4)*68 + col];
            uint32_t b0h, b0l, b1h, b1l;
            split_tf32(b0, b0h, b0l);
            split_tf32(b1, b1h, b1l);
            mma_tf32(ac2[nt], a, b0h, b1h);
            mma_tf32(ac2[nt], a, b0l, b1l);
        }
    }
    __syncthreads();   // all C1 reads of pf done before overwrite with X2

    // ---- C1 epilogue: h1 -> xtrain (gmem) ; relu(h1) -> pf (=X2) -----------
    {
        float i0 = inv[row0], i1 = inv[row1];
        #pragma unroll
        for (int nt = 0; nt < 4; nt++) {
            int c0 = cb2 + nt*8 + 2*tig;
            float bc0 = __ldg(&b1[c0]), bc1 = __ldg(&b1[c0 + 1]);
            float v00 = ac2[nt][0]*i0 + skp[row0*68 + c0]     + bc0;
            float v01 = ac2[nt][1]*i0 + skp[row0*68 + c0 + 1] + bc1;
            float v10 = ac2[nt][2]*i1 + skp[row1*68 + c0]     + bc0;
            float v11 = ac2[nt][3]*i1 + skp[row1*68 + c0 + 1] + bc1;
            if (xtrain) {
                if (row0 < NPG)
                    *(float2*)&xtrain[(size_t)(g*NPG + row0)*HC + c0] = make_float2(v00, v01);
                if (row1 < NPG)
                    *(float2*)&xtrain[(size_t)(g*NPG + row1)*HC + c0] = make_float2(v10, v11);
            }
            pf[row0*68 + c0]     = fmaxf(v00, 0.f);
            pf[row0*68 + c0 + 1] = fmaxf(v01, 0.f);
            pf[row1*68 + c0]     = fmaxf(v10, 0.f);
            pf[row1*68 + c0 + 1] = fmaxf(v11, 0.f);
        }
    }
    __syncthreads();   // X2 complete

    // ================= B2: P2 = X2 @ [W2l|W2r], KD=64, 4 stages ==============
    #pragma unroll
    for (int i = 0; i < 8; i++)
        #pragma unroll
        for (int j = 0; j < 4; j++) acc[i][j] = 0.f;

    for (int s = 0; s < 4; s++) {
        int kt = s*16;
        __syncthreads();
        for (int i = t; i < 16*128; i += 384) {
            int kk = i >> 7, c = i & 127;
            int kg = kt + kk;
            float wv = (c < 64) ? W2l[kg*64 + c] : W2r[kg*64 + (c - 64)];
            uint32_t h, l; split_tf32(wv, h, l);
            whi[kk*136 + c] = h; wlo[kk*136 + c] = l;
        }
        __syncthreads();
        #pragma unroll
        for (int kt2 = 0; kt2 < 16; kt2 += 8) {
            int kA = kt + kt2;
            float a0 = pf[row0*68 + kA + tig];
            float a1 = pf[row1*68 + kA + tig];
            float a2 = pf[row0*68 + kA + tig + 4];
            float a3 = pf[row1*68 + kA + tig + 4];
            uint32_t ah[4], al[4];
            split_tf32(a0, ah[0], al[0]);
            split_tf32(a1, ah[1], al[1]);
            split_tf32(a2, ah[2], al[2]);
            split_tf32(a3, ah[3], al[3]);
            #pragma unroll
            for (int nt = 0; nt < 8; nt++) {
                int col = cbase + nt*8 + gid;
                uint32_t b0h = whi[(kt2 + tig)*136 + col];
                uint32_t b1h = whi[(kt2 + tig + 4)*136 + col];
                uint32_t b0l = wlo[(kt2 + tig)*136 + col];
                uint32_t b1l = wlo[(kt2 + tig + 4)*136 + col];
                mma_tf32(acc[nt], ah, b0h, b1h);
                mma_tf32(acc[nt], ah, b0l, b1l);
                mma_tf32(acc[nt], al, b0h, b1h);
            }
        }
    }
    __syncthreads();   // all B2 reads of pf(X2) done before overwrite with P2

    // ---- B2 epilogue: P2 -> pf / skp ----
    {
        float* dst = (ch == 0) ? pf : skp;
        #pragma unroll
        for (int nt = 0; nt < 8; nt++) {
            int c = nt*8 + 2*tig;
            *(float2*)&dst[row0*68 + c] = make_float2(acc[nt][0], acc[nt][1]);
            *(float2*)&dst[row1*68 + c] = make_float2(acc[nt][2], acc[nt][3]);
        }
    }
    __syncthreads();

    // ================= C2: H2 = rowmean(A @ P2[:,0:64]) + skp + b2 ===========
    #pragma unroll
    for (int i = 0; i < 4; i++)
        #pragma unroll
        for (int j = 0; j < 4; j++) ac2[i][j] = 0.f;

    #pragma unroll
    for (int k8 = 0; k8 < 96; k8 += 8) {
        uint32_t a[4];
        a[0] = AX[row0*100 + k8 + tig];
        a[1] = AX[row1*100 + k8 + tig];
        a[2] = AX[row0*100 + k8 + tig + 4];
        a[3] = AX[row1*100 + k8 + tig + 4];
        #pragma unroll
        for (int nt = 0; nt < 4; nt++) {
            int col = cb2 + nt*8 + gid;
            float b0 = pf[(k8 + tig)*68 + col];
            float b1 = pf[(k8 + tig + 4)*68 + col];
            uint32_t b0h, b0l, b1h, b1l;
            split_tf32(b0, b0h, b0l);
            split_tf32(b1, b1h, b1l);
            mma_tf32(ac2[nt], a, b0h, b1h);
            mma_tf32(ac2[nt], a, b0l, b1l);
        }
    }

    // ---- C2 epilogue + fused sort-pool ----
    {
        float i0 = inv[row0], i1 = inv[row1];
        #pragma unroll
        for (int nt = 0; nt < 4; nt++) {
            int c0 = cb2 + nt*8 + 2*tig;
            float bc0 = __ldg(&b2[c0]), bc1 = __ldg(&b2[c0 + 1]);
            ac2[nt][0] = ac2[nt][0]*i0 + skp[row0*68 + c0]     + bc0;
            ac2[nt][1] = ac2[nt][1]*i0 + skp[row0*68 + c0 + 1] + bc1;
            ac2[nt][2] = ac2[nt][2]*i1 + skp[row1*68 + c0]     + bc0;
            ac2[nt][3] = ac2[nt][3]*i1 + skp[row1*68 + c0 + 1] + bc1;
        }
    }
    if (ch == 1 && tig == 3) {           // channel 63
        if (row0 < NPG) key[row0] = ac2[3][1];
        if (row1 < NPG) key[row1] = ac2[3][3];
    }
    __syncthreads();
    if (t < NPG) {
        float v = key[t];
        int rank = 0;
        for (int j = 0; j < NPG; j++) {
            float u = key[j];
            rank += (u > v) || (u == v && j < t);
        }
        rrank[t] = rank;
    }
    __syncthreads();
    {
        int rk0 = (row0 < NPG) ? rrank[row0] : KP;
        int rk1 = (row1 < NPG) ? rrank[row1] : KP;
        #pragma unroll
        for (int nt = 0; nt < 4; nt++) {
            int c0 = cb2 + nt*8 + 2*tig;
            if (rk0 < KP)
                *(float2*)&g_pool[(size_t)g*POOLW + rk0*HC + c0] =
                    make_float2(ac2[nt][0], ac2[nt][1]);
            if (rk1 < KP)
                *(float2*)&g_pool[(size_t)g*POOLW + rk1*HC + c0] =
                    make_float2(ac2[nt][2], ac2[nt][3]);
        }
    }
}

// ---------------- head1: partial pool @ Wl1 -> g_h512 (atomic) ---------------
// grid = 8 graph-tiles x 70 k-chunks = 560 blocks. Both smem tiles k-contiguous
// (pitch 68) -> float4 inner loop: ws reads phase-conflict-free, ps broadcast.
__global__ __launch_bounds__(256) void head1(const float* __restrict__ Wl1) {
    __shared__ float ws[64*68];      // [c][kk]
    __shared__ float ps[64*68];      // [graph][kk]
    int bt = blockIdx.x;
    int gt = bt & 7;                 // graph tile (64 graphs)
    int chunk = bt >> 3;             // k-chunk 0..69
    int t = threadIdx.x;
    int m0 = chunk*64;

    for (int i = t; i < 4096; i += 256) {
        int kk = i >> 6, c = i & 63;                     // gmem coalesced over c
        ws[c*68 + kk] = Wl1[(size_t)(m0 + kk)*64 + c];
    }
    for (int i = t; i < 4096; i += 256) {
        int gg = i >> 6, kk = i & 63;                    // gmem coalesced over kk
        ps[gg*68 + kk] = g_pool[(size_t)(gt*64 + gg)*POOLW + m0 + kk];
    }
    __syncthreads();

    int c = t & 63, gq = t >> 6;
    float acc[16];
    #pragma unroll
    for (int i = 0; i < 16; i++) acc[i] = 0.f;

    #pragma unroll 4
    for (int k4 = 0; k4 < 64; k4 += 4) {
        float4 w4 = *(const float4*)&ws[c*68 + k4];
        #pragma unroll
        for (int i = 0; i < 16; i++) {
            float4 p4 = *(const float4*)&ps[(gq + i*4)*68 + k4];
            acc[i] += p4.x*w4.x + p4.y*w4.y + p4.z*w4.z + p4.w*w4.w;
        }
    }
    #pragma unroll
    for (int i = 0; i < 16; i++)
        atomicAdd(&g_h512[(gt*64 + gq + i*4)*HC + c], acc[i]);
}

// ---------------- head2: (h + bl1) . Wl2 + bl2 -> sigmoid --------------------
__global__ __launch_bounds__(256) void head2(const float* __restrict__ bl1,
                                             const float* __restrict__ Wl2,
                                             const float* __restrict__ bl2,
                                             float* __restrict__ outG) {
    int g = blockIdx.x*8 + (threadIdx.x >> 5);
    int lane = threadIdx.x & 31;
    float v = (g_h512[g*HC + lane]      + bl1[lane])      * Wl2[lane]
            + (g_h512[g*HC + lane + 32] + bl1[lane + 32]) * Wl2[lane + 32];
    #pragma unroll
    for (int o = 16; o; o >>= 1) v += __shfl_xor_sync(0xffffffffu, v, o);
    if (lane == 0) outG[g] = 1.f / (1.f + expf(-(v + bl2[0])));
}

// ---------------------------------------------------------------------------
extern "C" void kernel_launch(void* const* d_in, const int* in_sizes, int n_in,
                              void* d_out, int out_size) {
    const float *x = 0, *W1l = 0, *W1r = 0, *W2l = 0, *W2r = 0;
    const float *Wl1 = 0, *bl2 = 0;
    const int   *ei = 0;
    int i5760 = 0, i4096 = 0;
    int idx64[8]; int n64 = 0;

    for (int i = 0; i < n_in; i++) {
        int sz = in_sizes[i];
        const float* p = (const float*)d_in[i];
        switch (sz) {
            case 4147200: x   = p; break;                       // [46080,90]
            case 1843200: ei  = (const int*)d_in[i]; break;     // [2,921600]
            case  286720: Wl1 = p; break;                       // [4480,64]
            case    5760: if (i5760++ == 0) W1l = p; else W1r = p; break;
            case    4096: if (i4096++ == 0) W2l = p; else W2r = p; break;
            case      64: if (n64 < 8) idx64[n64++] = i; break; // b1,b2,bl1,Wl2
            case       1: bl2 = p; break;
            default: break;                                     // batch unused
        }
    }
    const float *b1, *b2, *bl1, *Wl2;
    if (n_in > 0 && in_sizes[0] == 5760) {          // alphabetical (W* first)
        Wl2 = (const float*)d_in[idx64[0]];
        b1  = (const float*)d_in[idx64[1]];
        b2  = (const float*)d_in[idx64[2]];
        bl1 = (const float*)d_in[idx64[3]];
    } else {                                        // dict / signature order
        b1  = (const float*)d_in[idx64[0]];
        b2  = (const float*)d_in[idx64[1]];
        bl1 = (const float*)d_in[idx64[2]];
        Wl2 = (const float*)d_in[idx64[3]];
    }

    float* outG = (float*)d_out;
    float* xtp  = (out_size >= G + NTOT*HC) ? (float*)d_out + G : (float*)0;
    int E = 1843200 / 2;

    // (1) zero packed adjacency + head partials + detect edge dtype
    zeroA_kernel<<<540, 512>>>(ei);
    // (2) edge counts (byte-packed atomics, 2 edges/thread)
    edge_kernel<<<(E/2 + 255)/256, 256>>>(ei, E);
    // (3) conv1 + conv2 + sort-pool mega-fused
    conv_both<<<G, 384>>>(x, W1l, W1r, b1, W2l, W2r, b2, xtp);
    // (4) head GEMM partials, 560 blocks, float4 inner  [<- ncu capture slot]
    head1<<<560, 256>>>(Wl1);
    // (5) head reduction + sigmoid
    head2<<<G/8, 256>>>(bl1, Wl2, bl2, outG);
}

// round 17
// speedup vs baseline: 3.3264x; 1.0104x over previous
#include <cuda_runtime.h>
#include <math.h>
#include <stdint.h>

#define G    512
#define NPG  90
#define NTOT (G*NPG)      // 46080
#define FIN  90
#define HC   64
#define KP   70
#define POOLW (KP*HC)     // 4480
#define AW   24           // words per packed A row (96 bytes)

// ---------------- scratch (device globals; referenced ONLY in device code) --
__device__ uint32_t g_Au[G*NPG*AW];     // byte-packed edge counts, 4.4MB
__device__ float    g_pool[G*POOLW];    // sort-pooled features
__device__ float    g_h512[G*HC];       // head partials (pool @ Wl1)
__device__ uint32_t g_Whi[(FIN+HC)*128];// pre-split W (tf32 hi): W1 rows 0-89, W2 rows 90-153
__device__ uint32_t g_Wlo[(FIN+HC)*128];// pre-split W (tf32 lo)
__device__ int      g_mode;             // 1 = edge data is int64 (odd words zero)

// ---------------- tf32 helpers ----------------------------------------------
__device__ __forceinline__ uint32_t f2tf32(float x) {
    uint32_t r;
    asm("cvt.rna.tf32.f32 %0, %1;" : "=r"(r) : "f"(x));
    return r;
}
__device__ __forceinline__ void split_tf32(float x, uint32_t& hi, uint32_t& lo) {
    hi = f2tf32(x);
    lo = f2tf32(x - __uint_as_float(hi));
}
__device__ __forceinline__ void mma_tf32(float* d, const uint32_t* a,
                                         uint32_t b0, uint32_t b1) {
    asm volatile(
        "mma.sync.aligned.m16n8k8.row.col.f32.tf32.tf32.f32 "
        "{%0,%1,%2,%3},{%4,%5,%6,%7},{%8,%9},{%0,%1,%2,%3};"
        : "+f"(d[0]), "+f"(d[1]), "+f"(d[2]), "+f"(d[3])
        : "r"(a[0]), "r"(a[1]), "r"(a[2]), "r"(a[3]), "r"(b0), "r"(b1));
}

// ---------------- zero packed adjacency + head partials + dtype detect ------
__global__ void zeroA_kernel(const int* __restrict__ ei) {
    if (blockIdx.x == 0 && threadIdx.x < 32) {
        int lane = threadIdx.x;
        int nz = 0;
        for (int i = lane; i < 512; i += 32) nz |= ei[2*i + 1];
        unsigned any = __ballot_sync(0xffffffffu, nz != 0);
        if (lane == 0) g_mode = (any == 0);
    }
    int n = G*NPG*AW/4;
    uint4* p = (uint4*)g_Au;
    uint4 z = make_uint4(0u, 0u, 0u, 0u);
    for (int i = blockIdx.x*blockDim.x + threadIdx.x; i < n; i += gridDim.x*blockDim.x)
        p[i] = z;
    int nh = G*HC/4;
    float4* q = (float4*)g_h512;
    float4 zf = make_float4(0.f, 0.f, 0.f, 0.f);
    for (int i = blockIdx.x*blockDim.x + threadIdx.x; i < nh; i += gridDim.x*blockDim.x)
        q[i] = zf;
}

// ---------------- pre-split conv weights to tf32 hi/lo in gmem --------------
__global__ void presplit_kernel(const float* __restrict__ W1l,
                                const float* __restrict__ W1r,
                                const float* __restrict__ W2l,
                                const float* __restrict__ W2r) {
    int i = blockIdx.x*blockDim.x + threadIdx.x;
    if (i >= (FIN+HC)*128) return;
    int k = i >> 7, c = i & 127;
    float wv;
    if (k < FIN) wv = (c < 64) ? W1l[k*64 + c] : W1r[k*64 + (c - 64)];
    else { int k2 = k - FIN; wv = (c < 64) ? W2l[k2*64 + c] : W2r[k2*64 + (c - 64)]; }
    uint32_t h, l; split_tf32(wv, h, l);
    g_Whi[i] = h; g_Wlo[i] = l;
}

// ---------------- edge counts: 2 edges per thread ----------------------------
__global__ void edge_kernel(const int* __restrict__ ei, int E) {
    int e0 = (blockIdx.x*blockDim.x + threadIdx.x)*2;
    if (e0 >= E) return;
    int mode = g_mode;
    #pragma unroll
    for (int j = 0; j < 2; j++) {
        int e = e0 + j;
        if (e >= E) break;
        int s, d;
        if (mode) { s = ei[2*e]; d = ei[2*(E + e)]; }   // int64 storage
        else      { s = ei[e];   d = ei[E + e];      }  // int32 storage
        if ((unsigned)s >= NTOT || (unsigned)d >= NTOT) continue;
        int g  = d / NPG;
        int sl = s - g*NPG;
        int dl = d - g*NPG;
        if ((unsigned)sl >= NPG) continue;
        atomicAdd(&g_Au[(size_t)(g*NPG + dl)*AW + (sl >> 2)], 1u << (8*(sl & 3)));
    }
}

// ---------------- MEGA-fused: conv1 + conv2 + sort-pool, 1 block/graph ------
__global__ __launch_bounds__(384, 2) void conv_both(const float* __restrict__ X1,
                                                    const float* __restrict__ b1,
                                                    const float* __restrict__ b2,
                                                    float* __restrict__ xtrain) {
    __shared__ uint32_t AX[96*100];
    __shared__ uint32_t whi[16*136];
    __shared__ uint32_t wlo[16*136];
    __shared__ float    pf [96*68];
    __shared__ float    skp[96*68];
    __shared__ float    inv[96];
    __shared__ float    key[96];
    __shared__ int      rrank[96];

    int g = blockIdx.x, t = threadIdx.x;
    int lane = t & 31, w = t >> 5;
    float* Xs = (float*)AX;

    // ---- stage X1: zero ONLY pad regions (disjoint from data writes) ----
    for (int i = t; i < 96*6; i += 384) {            // k = 90..95, all rows
        int r = i / 6, k = 90 + (i - (i/6)*6);
        Xs[r*100 + k] = 0.f;
    }
    for (int i = t; i < 6*90; i += 384) {            // rows 90..95, k = 0..89
        int r = 90 + i / 90, k = i - (i/90)*90;
        Xs[r*100 + k] = 0.f;
    }
    for (int i = t; i < NPG*FIN; i += 384) {
        int r = i / FIN, k = i - (i/FIN)*FIN;
        Xs[r*100 + k] = X1[(size_t)(g*NPG + r)*FIN + k];
    }

    int gid = lane >> 2, tig = lane & 3;
    int wm  = (w >= 6) ? w - 6 : w;
    int ch  = (w >= 6) ? 1 : 0;
    int row0 = wm*16 + gid, row1 = row0 + 8;
    int cbase = ch*64;
    int cb2   = ch*32;

    float acc[8][4];
    #pragma unroll
    for (int i = 0; i < 8; i++)
        #pragma unroll
        for (int j = 0; j < 4; j++) acc[i][j] = 0.f;

    // ================= B1: P1 = X1 @ [W1l|W1r], KD=90, 6 stages ==============
    for (int s = 0; s < 6; s++) {
        int kt = s*16;
        __syncthreads();
        for (int i = t; i < 16*128; i += 384) {
            int kk = i >> 7, c = i & 127;
            int kg = kt + kk;
            uint32_t h = 0, l = 0;
            if (kg < FIN) { h = g_Whi[kg*128 + c]; l = g_Wlo[kg*128 + c]; }
            whi[kk*136 + c] = h; wlo[kk*136 + c] = l;
        }
        __syncthreads();
        #pragma unroll
        for (int kt2 = 0; kt2 < 16; kt2 += 8) {
            int kA = kt + kt2;
            float a0 = Xs[row0*100 + kA + tig];
            float a1 = Xs[row1*100 + kA + tig];
            float a2 = Xs[row0*100 + kA + tig + 4];
            float a3 = Xs[row1*100 + kA + tig + 4];
            uint32_t ah[4], al[4];
            split_tf32(a0, ah[0], al[0]);
            split_tf32(a1, ah[1], al[1]);
            split_tf32(a2, ah[2], al[2]);
            split_tf32(a3, ah[3], al[3]);
            #pragma unroll
            for (int nt = 0; nt < 8; nt++) {
                int col = cbase + nt*8 + gid;
                uint32_t b0h = whi[(kt2 + tig)*136 + col];
                uint32_t b1h = whi[(kt2 + tig + 4)*136 + col];
                uint32_t b0l = wlo[(kt2 + tig)*136 + col];
                uint32_t b1l = wlo[(kt2 + tig + 4)*136 + col];
                mma_tf32(acc[nt], ah, b0h, b1h);
                mma_tf32(acc[nt], ah, b0l, b1l);
                mma_tf32(acc[nt], al, b0h, b1h);
            }
        }
    }
    // ---- B1 epilogue: P1 -> pf / skp ----
    {
        float* dst = (ch == 0) ? pf : skp;
        #pragma unroll
        for (int nt = 0; nt < 8; nt++) {
            int c = nt*8 + 2*tig;
            *(float2*)&dst[row0*68 + c] = make_float2(acc[nt][0], acc[nt][1]);
            *(float2*)&dst[row1*68 + c] = make_float2(acc[nt][2], acc[nt][3]);
        }
    }
    __syncthreads();   // pf/skp ready; all B1 reads of AX(X1) done

    // ---- stage A (byte-packed -> tf32, exact) + rowsums via dp4a -----------
    const uint32_t* Ag = g_Au + (size_t)g*NPG*AW;
    {
        int wi = lane;
        #pragma unroll
        for (int i2 = 0; i2 < 8; i2++) {
            int r = w*8 + i2;
            uint32_t word = 0;
            if (wi < AW && r < NPG) word = Ag[r*AW + wi];
            if (wi < AW) {
                #pragma unroll
                for (int j = 0; j < 4; j++)
                    AX[r*100 + wi*4 + j] = f2tf32((float)((word >> (8*j)) & 0xFF));
            }
            int psum = __dp4a((int)word, 0x01010101, 0);
            #pragma unroll
            for (int o = 16; o; o >>= 1) psum += __shfl_xor_sync(0xffffffffu, psum, o);
            if (lane == 0) inv[r] = 1.0f / fmaxf((float)psum, 1.0f);
        }
    }
    __syncthreads();

    // ================= C1: H1 = rowmean(A @ P1[:,0:64]) + skp + b1 ===========
    float ac2[4][4];
    #pragma unroll
    for (int i = 0; i < 4; i++)
        #pragma unroll
        for (int j = 0; j < 4; j++) ac2[i][j] = 0.f;

    #pragma unroll
    for (int k8 = 0; k8 < 96; k8 += 8) {
        uint32_t a[4];
        a[0] = AX[row0*100 + k8 + tig];
        a[1] = AX[row1*100 + k8 + tig];
        a[2] = AX[row0*100 + k8 + tig + 4];
        a[3] = AX[row1*100 + k8 + tig + 4];
        #pragma unroll
        for (int nt = 0; nt < 4; nt++) {
            int col = cb2 + nt*8 + gid;
            float b0 = pf[(k8 + tig)*68 + col];
            float b1 = pf[(k8 + tig + 4)*68 + col];
            uint32_t b0h, b0l, b1h, b1l;
            split_tf32(b0, b0h, b0l);
            split_tf32(b1, b1h, b1l);
            mma_tf32(ac2[nt], a, b0h, b1h);
            mma_tf32(ac2[nt], a, b0l, b1l);
        }
    }
    __syncthreads();   // all C1 reads of pf done before overwrite with X2

    // ---- C1 epilogue: h1 -> xtrain (gmem) ; relu(h1) -> pf (=X2) -----------
    {
        float i0 = inv[row0], i1 = inv[row1];
        #pragma unroll
        for (int nt = 0; nt < 4; nt++) {
            int c0 = cb2 + nt*8 + 2*tig;
            float bc0 = __ldg(&b1[c0]), bc1 = __ldg(&b1[c0 + 1]);
            float v00 = ac2[nt][0]*i0 + skp[row0*68 + c0]     + bc0;
            float v01 = ac2[nt][1]*i0 + skp[row0*68 + c0 + 1] + bc1;
            float v10 = ac2[nt][2]*i1 + skp[row1*68 + c0]     + bc0;
            float v11 = ac2[nt][3]*i1 + skp[row1*68 + c0 + 1] + bc1;
            if (xtrain) {
                if (row0 < NPG)
                    *(float2*)&xtrain[(size_t)(g*NPG + row0)*HC + c0] = make_float2(v00, v01);
                if (row1 < NPG)
                    *(float2*)&xtrain[(size_t)(g*NPG + row1)*HC + c0] = make_float2(v10, v11);
            }
            pf[row0*68 + c0]     = fmaxf(v00, 0.f);
            pf[row0*68 + c0 + 1] = fmaxf(v01, 0.f);
            pf[row1*68 + c0]     = fmaxf(v10, 0.f);
            pf[row1*68 + c0 + 1] = fmaxf(v11, 0.f);
        }
    }
    __syncthreads();   // X2 complete

    // ================= B2: P2 = X2 @ [W2l|W2r], KD=64, 4 stages ==============
    #pragma unroll
    for (int i = 0; i < 8; i++)
        #pragma unroll
        for (int j = 0; j < 4; j++) acc[i][j] = 0.f;

    for (int s = 0; s < 4; s++) {
        int kt = s*16;
        __syncthreads();
        for (int i = t; i < 16*128; i += 384) {
            int kk = i >> 7, c = i & 127;
            int kg = FIN + kt + kk;                  // W2 rows at offset FIN
            whi[kk*136 + c] = g_Whi[kg*128 + c];
            wlo[kk*136 + c] = g_Wlo[kg*128 + c];
        }
        __syncthreads();
        #pragma unroll
        for (int kt2 = 0; kt2 < 16; kt2 += 8) {
            int kA = kt + kt2;
            float a0 = pf[row0*68 + kA + tig];
            float a1 = pf[row1*68 + kA + tig];
            float a2 = pf[row0*68 + kA + tig + 4];
            float a3 = pf[row1*68 + kA + tig + 4];
            uint32_t ah[4], al[4];
            split_tf32(a0, ah[0], al[0]);
            split_tf32(a1, ah[1], al[1]);
            split_tf32(a2, ah[2], al[2]);
            split_tf32(a3, ah[3], al[3]);
            #pragma unroll
            for (int nt = 0; nt < 8; nt++) {
                int col = cbase + nt*8 + gid;
                uint32_t b0h = whi[(kt2 + tig)*136 + col];
                uint32_t b1h = whi[(kt2 + tig + 4)*136 + col];
                uint32_t b0l = wlo[(kt2 + tig)*136 + col];
                uint32_t b1l = wlo[(kt2 + tig + 4)*136 + col];
                mma_tf32(acc[nt], ah, b0h, b1h);
                mma_tf32(acc[nt], ah, b0l, b1l);
                mma_tf32(acc[nt], al, b0h, b1h);
            }
        }
    }
    __syncthreads();   // all B2 reads of pf(X2) done before overwrite with P2

    // ---- B2 epilogue: P2 -> pf / skp ----
    {
        float* dst = (ch == 0) ? pf : skp;
        #pragma unroll
        for (int nt = 0; nt < 8; nt++) {
            int c = nt*8 + 2*tig;
            *(float2*)&dst[row0*68 + c] = make_float2(acc[nt][0], acc[nt][1]);
            *(float2*)&dst[row1*68 + c] = make_float2(acc[nt][2], acc[nt][3]);
        }
    }
    __syncthreads();

    // ================= C2: H2 = rowmean(A @ P2[:,0:64]) + skp + b2 ===========
    #pragma unroll
    for (int i = 0; i < 4; i++)
        #pragma unroll
        for (int j = 0; j < 4; j++) ac2[i][j] = 0.f;

    #pragma unroll
    for (int k8 = 0; k8 < 96; k8 += 8) {
        uint32_t a[4];
        a[0] = AX[row0*100 + k8 + tig];
        a[1] = AX[row1*100 + k8 + tig];
        a[2] = AX[row0*100 + k8 + tig + 4];
        a[3] = AX[row1*100 + k8 + tig + 4];
        #pragma unroll
        for (int nt = 0; nt < 4; nt++) {
            int col = cb2 + nt*8 + gid;
            float b0 = pf[(k8 + tig)*68 + col];
            float b1 = pf[(k8 + tig + 4)*68 + col];
            uint32_t b0h, b0l, b1h, b1l;
            split_tf32(b0, b0h, b0l);
            split_tf32(b1, b1h, b1l);
            mma_tf32(ac2[nt], a, b0h, b1h);
            mma_tf32(ac2[nt], a, b0l, b1l);
        }
    }

    // ---- C2 epilogue + fused sort-pool ----
    {
        float i0 = inv[row0], i1 = inv[row1];
        #pragma unroll
        for (int nt = 0; nt < 4; nt++) {
            int c0 = cb2 + nt*8 + 2*tig;
            float bc0 = __ldg(&b2[c0]), bc1 = __ldg(&b2[c0 + 1]);
            ac2[nt][0] = ac2[nt][0]*i0 + skp[row0*68 + c0]     + bc0;
            ac2[nt][1] = ac2[nt][1]*i0 + skp[row0*68 + c0 + 1] + bc1;
            ac2[nt][2] = ac2[nt][2]*i1 + skp[row1*68 + c0]     + bc0;
            ac2[nt][3] = ac2[nt][3]*i1 + skp[row1*68 + c0 + 1] + bc1;
        }
    }
    if (ch == 1 && tig == 3) {           // channel 63
        if (row0 < NPG) key[row0] = ac2[3][1];
        if (row1 < NPG) key[row1] = ac2[3][3];
    }
    __syncthreads();
    if (t < NPG) {
        float v = key[t];
        int rank = 0;
        for (int j = 0; j < NPG; j++) {
            float u = key[j];
            rank += (u > v) || (u == v && j < t);
        }
        rrank[t] = rank;
    }
    __syncthreads();
    {
        int rk0 = (row0 < NPG) ? rrank[row0] : KP;
        int rk1 = (row1 < NPG) ? rrank[row1] : KP;
        #pragma unroll
        for (int nt = 0; nt < 4; nt++) {
            int c0 = cb2 + nt*8 + 2*tig;
            if (rk0 < KP)
                *(float2*)&g_pool[(size_t)g*POOLW + rk0*HC + c0] =
                    make_float2(ac2[nt][0], ac2[nt][1]);
            if (rk1 < KP)
                *(float2*)&g_pool[(size_t)g*POOLW + rk1*HC + c0] =
                    make_float2(ac2[nt][2], ac2[nt][3]);
        }
    }
}

// ---------------- head1: partial pool @ Wl1 -> g_h512 (atomic) ---------------
// grid = 8 graph-tiles x 35 k-chunks(128) = 280 blocks, 512 threads.
// 67.6KB smem -> 3 blocks/SM. float4 inner; ws phase-conflict-free, ps bcast.
__global__ __launch_bounds__(512) void head1(const float* __restrict__ Wl1) {
    __shared__ float ws[64*132];     // [c][kk], pitch 132 (= 4 mod 32)
    __shared__ float ps[64*132];     // [graph][kk]
    int bt = blockIdx.x;
    int gt = bt & 7;                 // graph tile (64 graphs)
    int chunk = bt >> 3;             // k-chunk 0..34 (128 k each)
    int t = threadIdx.x;
    int m0 = chunk*128;

    for (int i = t; i < 8192; i += 512) {
        int kk = i >> 6, c = i & 63;                     // gmem coalesced over c
        ws[c*132 + kk] = Wl1[(size_t)(m0 + kk)*64 + c];
    }
    for (int i = t; i < 8192; i += 512) {
        int gg = i >> 7, kk = i & 127;                   // gmem coalesced over kk
        ps[gg*132 + kk] = g_pool[(size_t)(gt*64 + gg)*POOLW + m0 + kk];
    }
    __syncthreads();

    int c = t & 63, gq = t >> 6;     // gq 0..7, graphs gq + 8i
    float acc[8];
    #pragma unroll
    for (int i = 0; i < 8; i++) acc[i] = 0.f;

    #pragma unroll 4
    for (int k4 = 0; k4 < 128; k4 += 4) {
        float4 w4 = *(const float4*)&ws[c*132 + k4];
        #pragma unroll
        for (int i = 0; i < 8; i++) {
            float4 p4 = *(const float4*)&ps[(gq + i*8)*132 + k4];
            acc[i] += p4.x*w4.x + p4.y*w4.y + p4.z*w4.z + p4.w*w4.w;
        }
    }
    #pragma unroll
    for (int i = 0; i < 8; i++)
        atomicAdd(&g_h512[(gt*64 + gq + i*8)*HC + c], acc[i]);
}

// ---------------- head2: (h + bl1) . Wl2 + bl2 -> sigmoid --------------------
__global__ __launch_bounds__(256) void head2(const float* __restrict__ bl1,
                                             const float* __restrict__ Wl2,
                                             const float* __restrict__ bl2,
                                             float* __restrict__ outG) {
    int g = blockIdx.x*8 + (threadIdx.x >> 5);
    int lane = threadIdx.x & 31;
    float v = (g_h512[g*HC + lane]      + bl1[lane])      * Wl2[lane]
            + (g_h512[g*HC + lane + 32] + bl1[lane + 32]) * Wl2[lane + 32];
    #pragma unroll
    for (int o = 16; o; o >>= 1) v += __shfl_xor_sync(0xffffffffu, v, o);
    if (lane == 0) outG[g] = 1.f / (1.f + expf(-(v + bl2[0])));
}

// ---------------------------------------------------------------------------
extern "C" void kernel_launch(void* const* d_in, const int* in_sizes, int n_in,
                              void* d_out, int out_size) {
    const float *x = 0, *W1l = 0, *W1r = 0, *W2l = 0, *W2r = 0;
    const float *Wl1 = 0, *bl2 = 0;
    const int   *ei = 0;
    int i5760 = 0, i4096 = 0;
    int idx64[8]; int n64 = 0;

    for (int i = 0; i < n_in; i++) {
        int sz = in_sizes[i];
        const float* p = (const float*)d_in[i];
        switch (sz) {
            case 4147200: x   = p; break;                       // [46080,90]
            case 1843200: ei  = (const int*)d_in[i]; break;     // [2,921600]
            case  286720: Wl1 = p; break;                       // [4480,64]
            case    5760: if (i5760++ == 0) W1l = p; else W1r = p; break;
            case    4096: if (i4096++ == 0) W2l = p; else W2r = p; break;
            case      64: if (n64 < 8) idx64[n64++] = i; break; // b1,b2,bl1,Wl2
            case       1: bl2 = p; break;
            default: break;                                     // batch unused
        }
    }
    const float *b1, *b2, *bl1, *Wl2;
    if (n_in > 0 && in_sizes[0] == 5760) {          // alphabetical (W* first)
        Wl2 = (const float*)d_in[idx64[0]];
        b1  = (const float*)d_in[idx64[1]];
        b2  = (const float*)d_in[idx64[2]];
        bl1 = (const float*)d_in[idx64[3]];
    } else {                                        // dict / signature order
        b1  = (const float*)d_in[idx64[0]];
        b2  = (const float*)d_in[idx64[1]];
        bl1 = (const float*)d_in[idx64[2]];
        Wl2 = (const float*)d_in[idx64[3]];
    }

    float* outG = (float*)d_out;
    float* xtp  = (out_size >= G + NTOT*HC) ? (float*)d_out + G : (float*)0;
    int E = 1843200 / 2;

    // (1) zero packed adjacency + head partials + detect edge dtype
    zeroA_kernel<<<540, 512>>>(ei);
    // (2) edge counts (byte-packed atomics, 2 edges/thread)
    edge_kernel<<<(E/2 + 255)/256, 256>>>(ei, E);
    // (3) pre-split conv weights into gmem tf32 hi/lo
    presplit_kernel<<<((FIN+HC)*128 + 255)/256, 256>>>(W1l, W1r, W2l, W2r);
    // (4) conv1 + conv2 + sort-pool mega-fused  [<- ncu capture slot]
    conv_both<<<G, 384>>>(x, b1, b2, xtp);
    // (5) head GEMM partials, 280 blocks x 512 thr, 128-k chunks
    head1<<<280, 512>>>(Wl1);
    // (6) head reduction + sigmoid
    head2<<<G/8, 256>>>(bl1, Wl2, bl2, outG);
}